// round 4
// baseline (speedup 1.0000x reference)
#include <cuda_runtime.h>
#include <math.h>
#include <stdint.h>

// ---------------- problem constants ----------------
constexpr int B_  = 8;
constexpr int S_  = 512;
constexpr int E_  = 384;
constexpr int H_  = 7;
constexpr int D_  = 54;
constexpr int L_  = 7;
constexpr int V_  = 32000;
constexpr int FF_ = 6 * E_;          // 2304
constexpr int BS_ = B_ * S_;         // 4096
constexpr int HD_ = H_ * D_;         // 378
constexpr int HB_ = 192;             // padded head block: q(64)|k(64)|v(64)
constexpr int QLD_ = H_ * HB_;       // 1344, qkv row width
constexpr float EPS_ = 1e-5f;

// ---------------- scratch (static device memory; no allocation) ----------------
__device__ float g_x   [BS_ * E_];
__device__ float g_xn  [BS_ * E_];
__device__ float g_qkv [BS_ * QLD_];                 // fused padded qkv
__device__ float g_wqkv[L_ * E_ * QLD_];             // repacked qkv weights
__device__ float g_bqkv[L_ * QLD_];
__device__ float g_attn[(size_t)B_ * H_ * S_ * S_];  // [b,h,s,s]
__device__ float g_ocat[BS_ * HD_];
__device__ float g_h   [BS_ * FF_];
__device__ float g_loss;

#define FLAG_TRANSB 1
#define FLAG_ACC    2
#define FLAG_GELU   4

__device__ __forceinline__ float gelu_f(float x) {
    return 0.5f * x * (1.0f + erff(x * 0.70710678118654752f));
}
__device__ __forceinline__ uint32_t f2tf32(float x) {
    uint32_t r;
    asm("cvt.rna.tf32.f32 %0, %1;" : "=r"(r) : "f"(x));
    return r;
}

// =====================================================================
// tf32 tensor-core GEMM, templated tile width.
// BM=128 fixed (all M here are multiples of 128, grid.y = M/128 exact).
// BN=128: 8 warps 4x2, warp tile 32x64 (NT=8).  BN=64: warp tile 32x32 (NT=4).
// Batched via z -> (z/zdiv, z%zdiv) with two strides per operand.
// =====================================================================
template<int BN, int NT>
__global__ void __launch_bounds__(256, (BN == 64 ? 2 : 1))
tc_gemm(const float* __restrict__ A, const float* __restrict__ Bm,
        const float* __restrict__ bias, float* __restrict__ C,
        int M, int N, int Nb, int K,
        int lda, int ldb, int ldc, int zdiv,
        long long sA1, long long sA2, long long sB1, long long sB2,
        long long sC1, long long sC2,
        float alpha, int flags)
{
    constexpr int BM = 128, BK = 16;
    constexpr int ASTR = BM + 4;
    constexpr int BSTR = BN + 4;
    constexpr int BEL  = BN * BK / 256;   // B staging elems per thread (8 or 4)

    __shared__ uint32_t As[2][BK * ASTR];
    __shared__ uint32_t Bs[2][BK * BSTR];

    {
        const int z = blockIdx.z;
        const int zq = z / zdiv, zr = z - zq * zdiv;
        A  += (long long)zq * sA1 + (long long)zr * sA2;
        Bm += (long long)zq * sB1 + (long long)zr * sB2;
        C  += (long long)zq * sC1 + (long long)zr * sC2;
    }

    const int row0 = blockIdx.y * BM;
    const int col0 = blockIdx.x * BN;
    const int tid  = threadIdx.x;
    const int warp = tid >> 5;
    const int lane = tid & 31;
    const int wm = (warp >> 1) * 32;
    const int wn = (warp & 1) * (BN / 2);
    const int lr = lane >> 2;
    const int lc = lane & 3;
    const bool transB = (flags & FLAG_TRANSB);
    const bool a4 = ((lda & 3) == 0);
    const bool a2 = ((lda & 1) == 0);
    const bool b4 = ((ldb & 3) == 0);
    const bool nfull = (col0 + BN <= Nb);

    float acc[2][NT][4];
#pragma unroll
    for (int mt = 0; mt < 2; mt++)
#pragma unroll
        for (int nt = 0; nt < NT; nt++)
#pragma unroll
            for (int c = 0; c < 4; c++) acc[mt][nt][c] = 0.f;

    float aR[8], bR[BEL];
    const int nk = (K + BK - 1) / BK;

    auto loadA = [&](int k0, bool kfull) {
        if (kfull && a4) {
#pragma unroll
            for (int i = 0; i < 2; i++) {
                int e = tid + i * 256;
                int m = e >> 2, k4 = (e & 3) << 2;
                float4 v = *reinterpret_cast<const float4*>(
                    A + (long long)(row0 + m) * lda + k0 + k4);
                aR[i*4+0] = v.x; aR[i*4+1] = v.y; aR[i*4+2] = v.z; aR[i*4+3] = v.w;
            }
        } else if (kfull && a2) {
#pragma unroll
            for (int i = 0; i < 4; i++) {
                int e = tid + i * 256;
                int m = e >> 3, k2 = (e & 7) << 1;
                float2 v = *reinterpret_cast<const float2*>(
                    A + (long long)(row0 + m) * lda + k0 + k2);
                aR[i*2+0] = v.x; aR[i*2+1] = v.y;
            }
        } else {
#pragma unroll
            for (int i = 0; i < 8; i++) {
                int e = tid + i * 256;
                int m = e >> 4, k = e & 15;
                aR[i] = (k0 + k < K) ? A[(long long)(row0 + m) * lda + k0 + k] : 0.f;
            }
        }
    };
    auto stsA = [&](bool kfull, int buf) {
        if (kfull && a4) {
#pragma unroll
            for (int i = 0; i < 2; i++) {
                int e = tid + i * 256;
                int m = e >> 2, k4 = (e & 3) << 2;
#pragma unroll
                for (int j = 0; j < 4; j++)
                    As[buf][(k4 + j) * ASTR + m] = f2tf32(aR[i*4+j]);
            }
        } else if (kfull && a2) {
#pragma unroll
            for (int i = 0; i < 4; i++) {
                int e = tid + i * 256;
                int m = e >> 3, k2 = (e & 7) << 1;
                As[buf][(k2 + 0) * ASTR + m] = f2tf32(aR[i*2+0]);
                As[buf][(k2 + 1) * ASTR + m] = f2tf32(aR[i*2+1]);
            }
        } else {
#pragma unroll
            for (int i = 0; i < 8; i++) {
                int e = tid + i * 256;
                int m = e >> 4, k = e & 15;
                As[buf][k * ASTR + m] = f2tf32(aR[i]);
            }
        }
    };
    auto loadB = [&](int k0, bool kfull) {
        const bool fast = kfull && nfull && b4;
        if (transB) {
            if (fast) {
#pragma unroll
                for (int i = 0; i < BEL / 4; i++) {
                    int e = tid + i * 256;
                    int n = e >> 2, k4 = (e & 3) << 2;
                    float4 v = *reinterpret_cast<const float4*>(
                        Bm + (long long)(col0 + n) * ldb + k0 + k4);
                    bR[i*4+0] = v.x; bR[i*4+1] = v.y; bR[i*4+2] = v.z; bR[i*4+3] = v.w;
                }
            } else {
#pragma unroll
                for (int i = 0; i < BEL; i++) {
                    int e = tid + i * 256;
                    int n = e >> 4, k = e & 15;
                    bR[i] = (col0 + n < Nb && k0 + k < K)
                          ? Bm[(long long)(col0 + n) * ldb + k0 + k] : 0.f;
                }
            }
        } else {
            if (fast) {
#pragma unroll
                for (int i = 0; i < BEL / 4; i++) {
                    int e = tid + i * 256;
                    int k = e / (BN / 4), n4 = (e % (BN / 4)) << 2;
                    float4 v = *reinterpret_cast<const float4*>(
                        Bm + (long long)(k0 + k) * ldb + col0 + n4);
                    bR[i*4+0] = v.x; bR[i*4+1] = v.y; bR[i*4+2] = v.z; bR[i*4+3] = v.w;
                }
            } else {
#pragma unroll
                for (int i = 0; i < BEL; i++) {
                    int e = tid + i * 256;
                    int k = e / BN, n = e % BN;
                    bR[i] = (k0 + k < K && col0 + n < Nb)
                          ? Bm[(long long)(k0 + k) * ldb + col0 + n] : 0.f;
                }
            }
        }
    };
    auto stsB = [&](bool kfull, int buf) {
        const bool fast = kfull && nfull && b4;
        if (transB) {
            if (fast) {
#pragma unroll
                for (int i = 0; i < BEL / 4; i++) {
                    int e = tid + i * 256;
                    int n = e >> 2, k4 = (e & 3) << 2;
#pragma unroll
                    for (int j = 0; j < 4; j++)
                        Bs[buf][(k4 + j) * BSTR + n] = f2tf32(bR[i*4+j]);
                }
            } else {
#pragma unroll
                for (int i = 0; i < BEL; i++) {
                    int e = tid + i * 256;
                    int n = e >> 4, k = e & 15;
                    Bs[buf][k * BSTR + n] = f2tf32(bR[i]);
                }
            }
        } else {
            if (fast) {
#pragma unroll
                for (int i = 0; i < BEL / 4; i++) {
                    int e = tid + i * 256;
                    int k = e / (BN / 4), n4 = (e % (BN / 4)) << 2;
                    uint4 w;
                    w.x = f2tf32(bR[i*4+0]); w.y = f2tf32(bR[i*4+1]);
                    w.z = f2tf32(bR[i*4+2]); w.w = f2tf32(bR[i*4+3]);
                    *reinterpret_cast<uint4*>(&Bs[buf][k * BSTR + n4]) = w;
                }
            } else {
#pragma unroll
                for (int i = 0; i < BEL; i++) {
                    int e = tid + i * 256;
                    int k = e / BN, n = e % BN;
                    Bs[buf][k * BSTR + n] = f2tf32(bR[i]);
                }
            }
        }
    };

    bool kf = (BK <= K);
    loadA(0, kf); loadB(0, kf);
    stsA(kf, 0);  stsB(kf, 0);
    __syncthreads();

    int buf = 0;
    for (int it = 0; it < nk; it++) {
        const int k0n = (it + 1) * BK;
        const bool kfn = (k0n + BK <= K);
        if (it + 1 < nk) { loadA(k0n, kfn); loadB(k0n, kfn); }

#pragma unroll
        for (int ks = 0; ks < 2; ks++) {
            const int kk = ks * 8;
            uint32_t af[2][4], bf[NT][2];
#pragma unroll
            for (int mt = 0; mt < 2; mt++) {
                int m0 = wm + mt * 16 + lr;
                af[mt][0] = As[buf][(kk + lc) * ASTR + m0];
                af[mt][1] = As[buf][(kk + lc) * ASTR + m0 + 8];
                af[mt][2] = As[buf][(kk + lc + 4) * ASTR + m0];
                af[mt][3] = As[buf][(kk + lc + 4) * ASTR + m0 + 8];
            }
#pragma unroll
            for (int nt = 0; nt < NT; nt++) {
                int n0 = wn + nt * 8 + lr;
                bf[nt][0] = Bs[buf][(kk + lc) * BSTR + n0];
                bf[nt][1] = Bs[buf][(kk + lc + 4) * BSTR + n0];
            }
#pragma unroll
            for (int mt = 0; mt < 2; mt++)
#pragma unroll
                for (int nt = 0; nt < NT; nt++) {
                    asm volatile(
                        "mma.sync.aligned.m16n8k8.row.col.f32.tf32.tf32.f32 "
                        "{%0,%1,%2,%3}, {%4,%5,%6,%7}, {%8,%9}, {%0,%1,%2,%3};"
                        : "+f"(acc[mt][nt][0]), "+f"(acc[mt][nt][1]),
                          "+f"(acc[mt][nt][2]), "+f"(acc[mt][nt][3])
                        : "r"(af[mt][0]), "r"(af[mt][1]),
                          "r"(af[mt][2]), "r"(af[mt][3]),
                          "r"(bf[nt][0]), "r"(bf[nt][1]));
                }
        }

        if (it + 1 < nk) {
            stsA(kfn, buf ^ 1); stsB(kfn, buf ^ 1);
            __syncthreads();
            buf ^= 1;
        }
    }

    // epilogue (rows always in range; bound N only)
#pragma unroll
    for (int mt = 0; mt < 2; mt++)
#pragma unroll
        for (int nt = 0; nt < NT; nt++) {
            int rb = row0 + wm + mt * 16 + lr;
            int cb = col0 + wn + nt * 8 + lc * 2;
#pragma unroll
            for (int h = 0; h < 2; h++) {
                int r = rb + h * 8;
#pragma unroll
                for (int j = 0; j < 2; j++) {
                    int c = cb + j;
                    if (c >= N) continue;
                    float vv = acc[mt][nt][h * 2 + j] * alpha;
                    if (bias) vv += bias[c];
                    if (flags & FLAG_GELU) vv = gelu_f(vv);
                    long long ci = (long long)r * ldc + c;
                    if (flags & FLAG_ACC) vv += C[ci];
                    C[ci] = vv;
                }
            }
        }
}

// ---------------- weight repack: Wq/Wk/Wv[L,H,E,D] -> Wp[L,E,H*192] ----------------
__global__ void repack_qkv(const float* __restrict__ Wq, const float* __restrict__ Wk,
                           const float* __restrict__ Wv, float* __restrict__ Wp)
{
    long long idx = (long long)blockIdx.x * 256 + threadIdx.x;
    const long long total = (long long)L_ * E_ * QLD_;
    if (idx >= total) return;
    int c = (int)(idx % QLD_);
    long long le = idx / QLD_;
    int e = (int)(le % E_);
    int l = (int)(le / E_);
    int h = c / HB_, r = c % HB_, s = r >> 6, d = r & 63;
    float v = 0.f;
    if (d < D_) {
        const float* W = (s == 0) ? Wq : (s == 1) ? Wk : Wv;
        v = W[(((long long)l * H_ + h) * E_ + e) * D_ + d];
    }
    Wp[idx] = v;
}
__global__ void repack_bias(const float* __restrict__ bq, const float* __restrict__ bk,
                            const float* __restrict__ bv, float* __restrict__ bp)
{
    int idx = blockIdx.x * 256 + threadIdx.x;
    if (idx >= L_ * QLD_) return;
    int c = idx % QLD_, l = idx / QLD_;
    int h = c / HB_, r = c % HB_, s = r >> 6, d = r & 63;
    float v = 0.f;
    if (d < D_) {
        const float* bb = (s == 0) ? bq : (s == 1) ? bk : bv;
        v = bb[((long long)l * H_ + h) * D_ + d];
    }
    bp[idx] = v;
}

// ---------------- pointwise / reduction kernels ----------------
__global__ void embed_kernel(const int* __restrict__ ids,
                             const float* __restrict__ tok,
                             const float* __restrict__ pos,
                             float* __restrict__ x)
{
    int row = blockIdx.x;
    int s = row % S_;
    long long id = ids[row];
    float* xr = x + (long long)row * E_;
    const float* tr = tok + id * E_;
    const float* pr = pos + (long long)s * E_;
    for (int i = threadIdx.x; i < E_; i += blockDim.x)
        xr[i] = tr[i] + pr[i];
}

__global__ void ln_kernel(const float* __restrict__ x,
                          const float* __restrict__ g,
                          const float* __restrict__ b,
                          float* __restrict__ y)
{
    int row = blockIdx.x;
    const float* xr = x + (long long)row * E_;
    float s = 0.f, ss = 0.f;
    for (int i = threadIdx.x; i < E_; i += 128) {
        float v = xr[i];
        s += v; ss += v * v;
    }
#pragma unroll
    for (int o = 16; o > 0; o >>= 1) {
        s  += __shfl_xor_sync(0xffffffffu, s, o);
        ss += __shfl_xor_sync(0xffffffffu, ss, o);
    }
    __shared__ float sh_s[4], sh_ss[4];
    int w = threadIdx.x >> 5;
    if ((threadIdx.x & 31) == 0) { sh_s[w] = s; sh_ss[w] = ss; }
    __syncthreads();
    s  = sh_s[0] + sh_s[1] + sh_s[2] + sh_s[3];
    ss = sh_ss[0] + sh_ss[1] + sh_ss[2] + sh_ss[3];
    float mean = s / E_;
    float var  = ss / E_ - mean * mean;
    float rstd = rsqrtf(var + EPS_);
    float* yr = y + (long long)row * E_;
    for (int i = threadIdx.x; i < E_; i += 128)
        yr[i] = (xr[i] - mean) * rstd * g[i] + b[i];
}

__global__ void softmax_causal(float* __restrict__ attn)
{
    int row = blockIdx.x * 8 + threadIdx.y;
    int lane = threadIdx.x;
    int qi = row % S_;
    float* p = attn + (long long)row * S_;
    int n = qi + 1;
    float mx = -1e30f;
    for (int j = lane; j < n; j += 32) mx = fmaxf(mx, p[j]);
#pragma unroll
    for (int o = 16; o > 0; o >>= 1) mx = fmaxf(mx, __shfl_xor_sync(0xffffffffu, mx, o));
    float sum = 0.f;
    for (int j = lane; j < n; j += 32) {
        float e = expf(p[j] - mx);
        p[j] = e;
        sum += e;
    }
#pragma unroll
    for (int o = 16; o > 0; o >>= 1) sum += __shfl_xor_sync(0xffffffffu, sum, o);
    float inv = 1.f / sum;
    for (int j = lane; j < n; j += 32) p[j] *= inv;
    for (int j = n + lane; j < S_; j += 32) p[j] = 0.f;
}

__global__ void loss_kernel(const float* __restrict__ logits,
                            const int* __restrict__ tgt,
                            float* __restrict__ acc)
{
    int row = blockIdx.x;
    const float* p = logits + (long long)row * V_;
    __shared__ float sh[8];
    float mx = -1e30f;
    for (int j = threadIdx.x; j < V_; j += 256) mx = fmaxf(mx, p[j]);
#pragma unroll
    for (int o = 16; o > 0; o >>= 1) mx = fmaxf(mx, __shfl_xor_sync(0xffffffffu, mx, o));
    int w = threadIdx.x >> 5;
    if ((threadIdx.x & 31) == 0) sh[w] = mx;
    __syncthreads();
    mx = sh[0];
#pragma unroll
    for (int i = 1; i < 8; i++) mx = fmaxf(mx, sh[i]);
    __syncthreads();
    float sum = 0.f;
    for (int j = threadIdx.x; j < V_; j += 256) sum += expf(p[j] - mx);
#pragma unroll
    for (int o = 16; o > 0; o >>= 1) sum += __shfl_xor_sync(0xffffffffu, sum, o);
    if ((threadIdx.x & 31) == 0) sh[w] = sum;
    __syncthreads();
    if (threadIdx.x == 0) {
        float tot = 0.f;
#pragma unroll
        for (int i = 0; i < 8; i++) tot += sh[i];
        float lse = mx + logf(tot);
        atomicAdd(acc, p[tgt[row]] - lse);
    }
}

__global__ void zero_loss(float* a) { *a = 0.f; }
__global__ void fin_loss(const float* a, float* out) { *out = -(*a) / (float)BS_; }

// ---------------- host driver ----------------
typedef long long ll;

static void gemm(bool big, const float* A, const float* Bm, const float* bias, float* C,
                 int M, int N, int Nb, int K, int lda, int ldb, int ldc,
                 int batch, int zdiv,
                 ll sA1, ll sA2, ll sB1, ll sB2, ll sC1, ll sC2,
                 float alpha, int flags)
{
    if (big) {
        dim3 grid((N + 127) / 128, M / 128, batch);
        tc_gemm<128, 8><<<grid, 256>>>(A, Bm, bias, C, M, N, Nb, K, lda, ldb, ldc,
                                       zdiv, sA1, sA2, sB1, sB2, sC1, sC2, alpha, flags);
    } else {
        dim3 grid((N + 63) / 64, M / 128, batch);
        tc_gemm<64, 4><<<grid, 256>>>(A, Bm, bias, C, M, N, Nb, K, lda, ldb, ldc,
                                      zdiv, sA1, sA2, sB1, sB2, sC1, sC2, alpha, flags);
    }
}

extern "C" void kernel_launch(void* const* d_in, const int* in_sizes, int n_in,
                              void* d_out, int out_size)
{
    const int*   input_ids = (const int*)d_in[0];
    const int*   targets   = (const int*)d_in[1];
    const float* tok_emb   = (const float*)d_in[2];
    const float* pos_emb   = (const float*)d_in[3];
    const float* Wq  = (const float*)d_in[4];
    const float* bq  = (const float*)d_in[5];
    const float* Wk  = (const float*)d_in[6];
    const float* bk  = (const float*)d_in[7];
    const float* Wv  = (const float*)d_in[8];
    const float* bv  = (const float*)d_in[9];
    const float* Wc  = (const float*)d_in[10];
    const float* bc  = (const float*)d_in[11];
    const float* g1  = (const float*)d_in[12];
    const float* b1  = (const float*)d_in[13];
    const float* g2  = (const float*)d_in[14];
    const float* b2  = (const float*)d_in[15];
    const float* W1  = (const float*)d_in[16];
    const float* bf1 = (const float*)d_in[17];
    const float* W2  = (const float*)d_in[18];
    const float* bf2 = (const float*)d_in[19];
    const float* gf   = (const float*)d_in[20];
    const float* bfin = (const float*)d_in[21];
    const float* Wout = (const float*)d_in[22];
    const float* bout = (const float*)d_in[23];
    float* out = (float*)d_out;

    float *x, *xn, *qkv, *wqkv, *bqkv, *attn, *ocat, *hbuf, *lossp;
    cudaGetSymbolAddress((void**)&x,    g_x);
    cudaGetSymbolAddress((void**)&xn,   g_xn);
    cudaGetSymbolAddress((void**)&qkv,  g_qkv);
    cudaGetSymbolAddress((void**)&wqkv, g_wqkv);
    cudaGetSymbolAddress((void**)&bqkv, g_bqkv);
    cudaGetSymbolAddress((void**)&attn, g_attn);
    cudaGetSymbolAddress((void**)&ocat, g_ocat);
    cudaGetSymbolAddress((void**)&hbuf, g_h);
    cudaGetSymbolAddress((void**)&lossp, g_loss);

    const float scale = 1.0f / sqrtf((float)D_);

    // weight repack (once per call)
    {
        long long total = (long long)L_ * E_ * QLD_;
        repack_qkv<<<(int)((total + 255) / 256), 256>>>(Wq, Wk, Wv, wqkv);
        repack_bias<<<(L_ * QLD_ + 255) / 256, 256>>>(bq, bk, bv, bqkv);
    }

    embed_kernel<<<BS_, 128>>>(input_ids, tok_emb, pos_emb, x);

    for (int l = 0; l < L_; l++) {
        ln_kernel<<<BS_, 128>>>(x, g1 + l * E_, b1 + l * E_, xn);

        // fused QKV: [4096,384] @ [384,1344]  (padded cols are zero -> zero output)
        gemm(true, xn, wqkv + (ll)l * E_ * QLD_, bqkv + (ll)l * QLD_, qkv,
             BS_, QLD_, QLD_, E_, E_, QLD_, QLD_,
             1, 1, 0, 0, 0, 0, 0, 0, 1.f, 0);

        // scores: z=(b,h);  q at col h*192, k at h*192+64, K=64 (zero-padded)
        gemm(true, qkv, qkv + 64, nullptr, attn,
             S_, S_, S_, 64, QLD_, QLD_, S_,
             B_ * H_, H_,
             (ll)S_ * QLD_, HB_, (ll)S_ * QLD_, HB_,
             (ll)H_ * S_ * S_, (ll)S_ * S_,
             scale, FLAG_TRANSB);

        {
            dim3 blk(32, 8);
            softmax_causal<<<(B_ * H_ * S_) / 8, blk>>>(attn);
        }

        // PV: o[b,s, h*54+d] = attn[b,h] @ v[b,h]   (writes directly into concat layout)
        gemm(false, attn, qkv + 128, nullptr, ocat,
             S_, D_, 64, S_, S_, QLD_, HD_,
             B_ * H_, H_,
             (ll)H_ * S_ * S_, (ll)S_ * S_, (ll)S_ * QLD_, HB_,
             (ll)S_ * HD_, D_,
             1.f, 0);

        // x += ocat @ Wc + bc
        gemm(false, ocat, Wc + (ll)l * HD_ * E_, bc + l * E_, x,
             BS_, E_, E_, HD_, HD_, E_, E_,
             1, 1, 0, 0, 0, 0, 0, 0, 1.f, FLAG_ACC);

        ln_kernel<<<BS_, 128>>>(x, g2 + l * E_, b2 + l * E_, xn);

        // h = gelu(xn @ W1 + bf1)
        gemm(true, xn, W1 + (ll)l * E_ * FF_, bf1 + (ll)l * FF_, hbuf,
             BS_, FF_, FF_, E_, E_, FF_, FF_,
             1, 1, 0, 0, 0, 0, 0, 0, 1.f, FLAG_GELU);

        // x += h @ W2 + bf2
        gemm(false, hbuf, W2 + (ll)l * FF_ * E_, bf2 + l * E_, x,
             BS_, E_, E_, FF_, FF_, E_, E_,
             1, 1, 0, 0, 0, 0, 0, 0, 1.f, FLAG_ACC);
    }

    ln_kernel<<<BS_, 128>>>(x, gf, bfin, xn);
    gemm(true, xn, Wout, bout, out,
         BS_, V_, V_, E_, E_, V_, V_,
         1, 1, 0, 0, 0, 0, 0, 0, 1.f, 0);

    const ll NLOG = (ll)BS_ * V_;
    if ((ll)out_size > NLOG) {
        zero_loss<<<1, 1>>>(lossp);
        loss_kernel<<<BS_, 256>>>(out, targets, lossp);
        fin_loss<<<1, 1>>>(lossp, out + NLOG);
    }
}

// round 10
// speedup vs baseline: 1.0998x; 1.0998x over previous
#include <cuda_runtime.h>
#include <math.h>
#include <stdint.h>

// ---------------- problem constants ----------------
constexpr int B_  = 8;
constexpr int S_  = 512;
constexpr int E_  = 384;
constexpr int H_  = 7;
constexpr int D_  = 54;
constexpr int L_  = 7;
constexpr int V_  = 32000;
constexpr int FF_ = 6 * E_;          // 2304
constexpr int BS_ = B_ * S_;         // 4096
constexpr int HD_ = H_ * D_;         // 378
constexpr int HB_ = 192;             // padded head block: q(64)|k(64)|v(64)
constexpr int QLD_ = H_ * HB_;       // 1344
constexpr float EPS_ = 1e-5f;

typedef long long ll;

// ---------------- scratch ----------------
__device__ float g_x   [BS_ * E_];
__device__ float g_xn  [BS_ * E_];
__device__ float g_qkv [BS_ * QLD_];
__device__ float g_wqkv[L_ * E_ * QLD_];
__device__ float g_bqkv[L_ * QLD_];
__device__ float g_attn[(size_t)B_ * H_ * S_ * S_];
__device__ float g_ocat[BS_ * HD_];
__device__ float g_h   [BS_ * FF_];
__device__ float g_loss;

#define FLAG_TRANSB 1
#define FLAG_ACC    2
#define FLAG_GELU   4

__device__ __forceinline__ float gelu_f(float x) {
    return 0.5f * x * (1.0f + erff(x * 0.70710678118654752f));
}
__device__ __forceinline__ uint32_t f2tf32(float x) {
    uint32_t r;
    asm("cvt.rna.tf32.f32 %0, %1;" : "=r"(r) : "f"(x));
    return r;
}

// =====================================================================
// tf32 mma.sync GEMM, two configs:
//   big  : BM=256, 8 warps 4x2, warp tile 64x64 (NT=8)
//   small: BM=128, 8 warps 2x4, warp tile 64x32 (NT=4)
// BN=128, BK=16 double-buffered. C = alpha*A@B (+bias)(+C), GELU/transB.
// Batched: z -> (z/zdiv, z%zdiv), two strides per operand.
// =====================================================================
template<int BM, int NT>
__global__ void __launch_bounds__(256, 1)
tc_gemm(const float* __restrict__ A, const float* __restrict__ Bm,
        const float* __restrict__ bias, float* __restrict__ C,
        int M, int N, int Nb, int K,
        int lda, int ldb, int ldc, int zdiv,
        ll sA1, ll sA2, ll sB1, ll sB2, ll sC1, ll sC2,
        float alpha, int flags)
{
    constexpr int BK = 16;
    constexpr int BN = 128;
    constexpr int MWARPS = BM / 64;            // 4 or 2
    constexpr int ASTR = BM + 4;               // %32 == 4 -> conflict-free frags
    constexpr int BSTR = BN + 4;               // 132
    constexpr int AW = BK * ASTR;
    constexpr int BW = BK * BSTR;
    constexpr int AE = BM / 16;                // A floats per thread per BK
    constexpr int AE4 = BM / 64;               // A float4 per thread

    extern __shared__ uint32_t sm[];

    {
        const int z = blockIdx.z;
        const int zq = z / zdiv, zr = z - zq * zdiv;
        A  += (ll)zq * sA1 + (ll)zr * sA2;
        Bm += (ll)zq * sB1 + (ll)zr * sB2;
        C  += (ll)zq * sC1 + (ll)zr * sC2;
    }

    const int row0 = blockIdx.y * BM;
    const int col0 = blockIdx.x * BN;
    const int tid  = threadIdx.x;
    const int warp = tid >> 5;
    const int lane = tid & 31;
    const int wm = (warp % MWARPS) * 64;
    const int wn = (warp / MWARPS) * (NT * 8);
    const int lr = lane >> 2;
    const int lc = lane & 3;
    const bool transB = (flags & FLAG_TRANSB);
    const bool a4 = ((lda & 3) == 0);
    const bool b4 = ((ldb & 3) == 0);
    const bool nfull = (col0 + BN <= Nb);

    float acc[4][NT][4];
#pragma unroll
    for (int mt = 0; mt < 4; mt++)
#pragma unroll
        for (int nt = 0; nt < NT; nt++)
#pragma unroll
            for (int c = 0; c < 4; c++) acc[mt][nt][c] = 0.f;

    float aR[AE], bR[8];
    const int nk = (K + BK - 1) / BK;

    auto loadA = [&](int k0) {
        if (a4 && (k0 + BK <= K)) {
#pragma unroll
            for (int i = 0; i < AE4; i++) {
                int e = tid + i * 256;
                int m = e >> 2, kq = e & 3;
                float4 v = *reinterpret_cast<const float4*>(
                    A + (ll)(row0 + m) * lda + k0 + kq * 4);
                aR[i*4+0] = v.x; aR[i*4+1] = v.y; aR[i*4+2] = v.z; aR[i*4+3] = v.w;
            }
        } else {
#pragma unroll
            for (int i = 0; i < AE; i++) {
                int e = tid + i * 256;
                int m = e >> 4, k = e & 15;
                aR[i] = (k0 + k < K) ? A[(ll)(row0 + m) * lda + k0 + k] : 0.f;
            }
        }
    };
    auto stsA = [&](int k0, uint32_t* As) {
        if (a4 && (k0 + BK <= K)) {
#pragma unroll
            for (int i = 0; i < AE4; i++) {
                int e = tid + i * 256;
                int m = e >> 2, kq = e & 3;
#pragma unroll
                for (int j = 0; j < 4; j++)
                    As[(kq * 4 + j) * ASTR + m] = f2tf32(aR[i*4+j]);
            }
        } else {
#pragma unroll
            for (int i = 0; i < AE; i++) {
                int e = tid + i * 256;
                int m = e >> 4, k = e & 15;
                As[k * ASTR + m] = f2tf32(aR[i]);
            }
        }
    };
    auto loadB = [&](int k0) {
        const bool kf = (k0 + BK <= K);
        if (transB) {
            if (kf && nfull && b4) {
#pragma unroll
                for (int i = 0; i < 2; i++) {
                    int e = tid + i * 256;
                    int n = e >> 2, kq = e & 3;
                    float4 v = *reinterpret_cast<const float4*>(
                        Bm + (ll)(col0 + n) * ldb + k0 + kq * 4);
                    bR[i*4+0] = v.x; bR[i*4+1] = v.y; bR[i*4+2] = v.z; bR[i*4+3] = v.w;
                }
            } else {
#pragma unroll
                for (int i = 0; i < 8; i++) {
                    int e = tid + i * 256;
                    int n = e >> 4, k = e & 15;
                    bR[i] = (col0 + n < Nb && k0 + k < K)
                          ? Bm[(ll)(col0 + n) * ldb + k0 + k] : 0.f;
                }
            }
        } else {
            if (kf && nfull && b4) {
#pragma unroll
                for (int i = 0; i < 2; i++) {
                    int e = tid + i * 256;
                    int k = e >> 5, n4 = (e & 31) << 2;
                    float4 v = *reinterpret_cast<const float4*>(
                        Bm + (ll)(k0 + k) * ldb + col0 + n4);
                    bR[i*4+0] = v.x; bR[i*4+1] = v.y; bR[i*4+2] = v.z; bR[i*4+3] = v.w;
                }
            } else {
#pragma unroll
                for (int i = 0; i < 8; i++) {
                    int e = tid + i * 256;
                    int k = e >> 7, n = e & 127;
                    bR[i] = (k0 + k < K && col0 + n < Nb)
                          ? Bm[(ll)(k0 + k) * ldb + col0 + n] : 0.f;
                }
            }
        }
    };
    auto stsB = [&](int k0, uint32_t* Bs) {
        const bool kf = (k0 + BK <= K);
        if (transB) {
            if (kf && nfull && b4) {
#pragma unroll
                for (int i = 0; i < 2; i++) {
                    int e = tid + i * 256;
                    int n = e >> 2, kq = e & 3;
#pragma unroll
                    for (int j = 0; j < 4; j++)
                        Bs[(kq * 4 + j) * BSTR + n] = f2tf32(bR[i*4+j]);
                }
            } else {
#pragma unroll
                for (int i = 0; i < 8; i++) {
                    int e = tid + i * 256;
                    int n = e >> 4, k = e & 15;
                    Bs[k * BSTR + n] = f2tf32(bR[i]);
                }
            }
        } else {
            if (kf && nfull && b4) {
#pragma unroll
                for (int i = 0; i < 2; i++) {
                    int e = tid + i * 256;
                    int k = e >> 5, n4 = (e & 31) << 2;
                    uint4 w;
                    w.x = f2tf32(bR[i*4+0]); w.y = f2tf32(bR[i*4+1]);
                    w.z = f2tf32(bR[i*4+2]); w.w = f2tf32(bR[i*4+3]);
                    *reinterpret_cast<uint4*>(&Bs[k * BSTR + n4]) = w;
                }
            } else {
#pragma unroll
                for (int i = 0; i < 8; i++) {
                    int e = tid + i * 256;
                    int k = e >> 7, n = e & 127;
                    Bs[k * BSTR + n] = f2tf32(bR[i]);
                }
            }
        }
    };

    loadA(0); loadB(0);
    stsA(0, sm); stsB(0, sm + AW);
    __syncthreads();

    int buf = 0;
    for (int it = 0; it < nk; it++) {
        if (it + 1 < nk) { loadA((it + 1) * BK); loadB((it + 1) * BK); }

        const uint32_t* As = sm + buf * (AW + BW);
        const uint32_t* Bs = As + AW;

#pragma unroll
        for (int ks = 0; ks < 2; ks++) {
            const int kk = ks * 8;
            uint32_t af[4][4], bf[NT][2];
#pragma unroll
            for (int mt = 0; mt < 4; mt++) {
                int m0 = wm + mt * 16 + lr;
                af[mt][0] = As[(kk + lc) * ASTR + m0];
                af[mt][1] = As[(kk + lc) * ASTR + m0 + 8];
                af[mt][2] = As[(kk + lc + 4) * ASTR + m0];
                af[mt][3] = As[(kk + lc + 4) * ASTR + m0 + 8];
            }
#pragma unroll
            for (int nt = 0; nt < NT; nt++) {
                int n0 = wn + nt * 8 + lr;
                bf[nt][0] = Bs[(kk + lc) * BSTR + n0];
                bf[nt][1] = Bs[(kk + lc + 4) * BSTR + n0];
            }
#pragma unroll
            for (int mt = 0; mt < 4; mt++)
#pragma unroll
                for (int nt = 0; nt < NT; nt++) {
                    asm volatile(
                        "mma.sync.aligned.m16n8k8.row.col.f32.tf32.tf32.f32 "
                        "{%0,%1,%2,%3}, {%4,%5,%6,%7}, {%8,%9}, {%0,%1,%2,%3};"
                        : "+f"(acc[mt][nt][0]), "+f"(acc[mt][nt][1]),
                          "+f"(acc[mt][nt][2]), "+f"(acc[mt][nt][3])
                        : "r"(af[mt][0]), "r"(af[mt][1]),
                          "r"(af[mt][2]), "r"(af[mt][3]),
                          "r"(bf[nt][0]), "r"(bf[nt][1]));
                }
        }

        if (it + 1 < nk) {
            uint32_t* Asn = sm + (buf ^ 1) * (AW + BW);
            stsA((it + 1) * BK, Asn);
            stsB((it + 1) * BK, Asn + AW);
            __syncthreads();
            buf ^= 1;
        }
    }

    // ---- epilogue ----
    const bool doacc = (flags & FLAG_ACC);
    const bool dogel = (flags & FLAG_GELU);
#pragma unroll
    for (int mt = 0; mt < 4; mt++)
#pragma unroll
        for (int nt = 0; nt < NT; nt++) {
            int rb = row0 + wm + mt * 16 + lr;
            int cb = col0 + wn + nt * 8 + lc * 2;
#pragma unroll
            for (int h = 0; h < 2; h++) {
                int r = rb + h * 8;
                int c = cb;
                if (c >= N) continue;
                float v0 = acc[mt][nt][h * 2 + 0] * alpha;
                float v1 = acc[mt][nt][h * 2 + 1] * alpha;
                if (bias) {
                    v0 += bias[c];
                    if (c + 1 < N) v1 += bias[c + 1];
                }
                if (dogel) { v0 = gelu_f(v0); v1 = gelu_f(v1); }
                float* Cp = C + (ll)r * ldc + c;
                if (c + 1 < N) {
                    if (doacc) {
                        float2 o = *reinterpret_cast<const float2*>(Cp);
                        v0 += o.x; v1 += o.y;
                    }
                    *reinterpret_cast<float2*>(Cp) = make_float2(v0, v1);
                } else {
                    if (doacc) v0 += Cp[0];
                    Cp[0] = v0;
                }
            }
        }
}

// ---------------- weight repack ----------------
__global__ void repack_qkv(const float* __restrict__ Wq, const float* __restrict__ Wk,
                           const float* __restrict__ Wv, float* __restrict__ Wp)
{
    ll idx = (ll)blockIdx.x * 256 + threadIdx.x;
    const ll total = (ll)L_ * E_ * QLD_;
    if (idx >= total) return;
    int c = (int)(idx % QLD_);
    ll le = idx / QLD_;
    int e = (int)(le % E_);
    int l = (int)(le / E_);
    int h = c / HB_, r = c % HB_, s = r >> 6, d = r & 63;
    float v = 0.f;
    if (d < D_) {
        const float* W = (s == 0) ? Wq : (s == 1) ? Wk : Wv;
        v = W[(((ll)l * H_ + h) * E_ + e) * D_ + d];
    }
    Wp[idx] = v;
}
__global__ void repack_bias(const float* __restrict__ bq, const float* __restrict__ bk,
                            const float* __restrict__ bv, float* __restrict__ bp)
{
    int idx = blockIdx.x * 256 + threadIdx.x;
    if (idx >= L_ * QLD_) return;
    int c = idx % QLD_, l = idx / QLD_;
    int h = c / HB_, r = c % HB_, s = r >> 6, d = r & 63;
    float v = 0.f;
    if (d < D_) {
        const float* bb = (s == 0) ? bq : (s == 1) ? bk : bv;
        v = bb[((ll)l * H_ + h) * D_ + d];
    }
    bp[idx] = v;
}

// ---------------- pointwise / reductions ----------------
__global__ void embed_kernel(const int* __restrict__ ids,
                             const float* __restrict__ tok,
                             const float* __restrict__ pos,
                             float* __restrict__ x)
{
    int row = blockIdx.x;
    int s = row % S_;
    ll id = ids[row];
    float* xr = x + (ll)row * E_;
    const float* tr = tok + id * E_;
    const float* pr = pos + (ll)s * E_;
    for (int i = threadIdx.x; i < E_; i += blockDim.x)
        xr[i] = tr[i] + pr[i];
}

__global__ void ln_kernel(const float* __restrict__ x,
                          const float* __restrict__ g,
                          const float* __restrict__ b,
                          float* __restrict__ y)
{
    int row = blockIdx.x;
    const float* xr = x + (ll)row * E_;
    float s = 0.f, ss = 0.f;
    for (int i = threadIdx.x; i < E_; i += 128) {
        float v = xr[i];
        s += v; ss += v * v;
    }
#pragma unroll
    for (int o = 16; o > 0; o >>= 1) {
        s  += __shfl_xor_sync(0xffffffffu, s, o);
        ss += __shfl_xor_sync(0xffffffffu, ss, o);
    }
    __shared__ float sh_s[4], sh_ss[4];
    int w = threadIdx.x >> 5;
    if ((threadIdx.x & 31) == 0) { sh_s[w] = s; sh_ss[w] = ss; }
    __syncthreads();
    s  = sh_s[0] + sh_s[1] + sh_s[2] + sh_s[3];
    ss = sh_ss[0] + sh_ss[1] + sh_ss[2] + sh_ss[3];
    float mean = s / E_;
    float var  = ss / E_ - mean * mean;
    float rstd = rsqrtf(var + EPS_);
    float* yr = y + (ll)row * E_;
    for (int i = threadIdx.x; i < E_; i += 128)
        yr[i] = (xr[i] - mean) * rstd * g[i] + b[i];
}

__global__ void softmax_causal(float* __restrict__ attn)
{
    int row = blockIdx.x * 8 + threadIdx.y;
    int lane = threadIdx.x;
    int qi = row % S_;
    float* p = attn + (ll)row * S_;
    int n = qi + 1;
    float mx = -1e30f;
    for (int j = lane; j < n; j += 32) mx = fmaxf(mx, p[j]);
#pragma unroll
    for (int o = 16; o > 0; o >>= 1) mx = fmaxf(mx, __shfl_xor_sync(0xffffffffu, mx, o));
    float sum = 0.f;
    for (int j = lane; j < n; j += 32) {
        float e = expf(p[j] - mx);
        p[j] = e;
        sum += e;
    }
#pragma unroll
    for (int o = 16; o > 0; o >>= 1) sum += __shfl_xor_sync(0xffffffffu, sum, o);
    float inv = 1.f / sum;
    for (int j = lane; j < n; j += 32) p[j] *= inv;
    for (int j = n + lane; j < S_; j += 32) p[j] = 0.f;
}

__global__ void loss_kernel(const float* __restrict__ logits,
                            const int* __restrict__ tgt,
                            float* __restrict__ acc)
{
    int row = blockIdx.x;
    const float* p = logits + (ll)row * V_;
    __shared__ float sh[8];
    float mx = -1e30f;
    for (int j = threadIdx.x; j < V_; j += 256) mx = fmaxf(mx, p[j]);
#pragma unroll
    for (int o = 16; o > 0; o >>= 1) mx = fmaxf(mx, __shfl_xor_sync(0xffffffffu, mx, o));
    int w = threadIdx.x >> 5;
    if ((threadIdx.x & 31) == 0) sh[w] = mx;
    __syncthreads();
    mx = sh[0];
#pragma unroll
    for (int i = 1; i < 8; i++) mx = fmaxf(mx, sh[i]);
    __syncthreads();
    float sum = 0.f;
    for (int j = threadIdx.x; j < V_; j += 256) sum += expf(p[j] - mx);
#pragma unroll
    for (int o = 16; o > 0; o >>= 1) sum += __shfl_xor_sync(0xffffffffu, sum, o);
    if ((threadIdx.x & 31) == 0) sh[w] = sum;
    __syncthreads();
    if (threadIdx.x == 0) {
        float tot = 0.f;
#pragma unroll
        for (int i = 0; i < 8; i++) tot += sh[i];
        float lse = mx + logf(tot);
        atomicAdd(acc, p[tgt[row]] - lse);
    }
}

__global__ void zero_loss(float* a) { *a = 0.f; }
__global__ void fin_loss(const float* a, float* out) { *out = -(*a) / (float)BS_; }

// ---------------- host driver ----------------
constexpr int SMEM_BIG   = 2 * (16 * (256 + 4) + 16 * 132) * 4;  // 50176 B
constexpr int SMEM_SMALL = 2 * (16 * (128 + 4) + 16 * 132) * 4;  // 33792 B

static void gemm(bool big, const float* A, const float* Bm, const float* bias, float* C,
                 int M, int N, int Nb, int K, int lda, int ldb, int ldc,
                 int batch, int zdiv,
                 ll sA1, ll sA2, ll sB1, ll sB2, ll sC1, ll sC2,
                 float alpha, int flags)
{
    if (big) {
        dim3 grid((N + 127) / 128, M / 256, batch);
        tc_gemm<256, 8><<<grid, 256, SMEM_BIG>>>(
            A, Bm, bias, C, M, N, Nb, K, lda, ldb, ldc,
            zdiv, sA1, sA2, sB1, sB2, sC1, sC2, alpha, flags);
    } else {
        dim3 grid((N + 127) / 128, M / 128, batch);
        tc_gemm<128, 4><<<grid, 256, SMEM_SMALL>>>(
            A, Bm, bias, C, M, N, Nb, K, lda, ldb, ldc,
            zdiv, sA1, sA2, sB1, sB2, sC1, sC2, alpha, flags);
    }
}

extern "C" void kernel_launch(void* const* d_in, const int* in_sizes, int n_in,
                              void* d_out, int out_size)
{
    const int*   input_ids = (const int*)d_in[0];
    const int*   targets   = (const int*)d_in[1];
    const float* tok_emb   = (const float*)d_in[2];
    const float* pos_emb   = (const float*)d_in[3];
    const float* Wq  = (const float*)d_in[4];
    const float* bq  = (const float*)d_in[5];
    const float* Wk  = (const float*)d_in[6];
    const float* bk  = (const float*)d_in[7];
    const float* Wv  = (const float*)d_in[8];
    const float* bv  = (const float*)d_in[9];
    const float* Wc  = (const float*)d_in[10];
    const float* bc  = (const float*)d_in[11];
    const float* g1  = (const float*)d_in[12];
    const float* b1  = (const float*)d_in[13];
    const float* g2  = (const float*)d_in[14];
    const float* b2  = (const float*)d_in[15];
    const float* W1  = (const float*)d_in[16];
    const float* bf1 = (const float*)d_in[17];
    const float* W2  = (const float*)d_in[18];
    const float* bf2 = (const float*)d_in[19];
    const float* gf   = (const float*)d_in[20];
    const float* bfin = (const float*)d_in[21];
    const float* Wout = (const float*)d_in[22];
    const float* bout = (const float*)d_in[23];
    float* out = (float*)d_out;

    cudaFuncSetAttribute(tc_gemm<256, 8>,
                         cudaFuncAttributeMaxDynamicSharedMemorySize, SMEM_BIG);
    cudaFuncSetAttribute(tc_gemm<128, 4>,
                         cudaFuncAttributeMaxDynamicSharedMemorySize, SMEM_SMALL);

    float *x, *xn, *qkv, *wqkv, *bqkv, *attn, *ocat, *hbuf, *lossp;
    cudaGetSymbolAddress((void**)&x,    g_x);
    cudaGetSymbolAddress((void**)&xn,   g_xn);
    cudaGetSymbolAddress((void**)&qkv,  g_qkv);
    cudaGetSymbolAddress((void**)&wqkv, g_wqkv);
    cudaGetSymbolAddress((void**)&bqkv, g_bqkv);
    cudaGetSymbolAddress((void**)&attn, g_attn);
    cudaGetSymbolAddress((void**)&ocat, g_ocat);
    cudaGetSymbolAddress((void**)&hbuf, g_h);
    cudaGetSymbolAddress((void**)&lossp, g_loss);

    const float scale = 1.0f / sqrtf((float)D_);

    {
        ll total = (ll)L_ * E_ * QLD_;
        repack_qkv<<<(int)((total + 255) / 256), 256>>>(Wq, Wk, Wv, wqkv);
        repack_bias<<<(L_ * QLD_ + 255) / 256, 256>>>(bq, bk, bv, bqkv);
    }

    embed_kernel<<<BS_, 128>>>(input_ids, tok_emb, pos_emb, x);

    for (int l = 0; l < L_; l++) {
        ln_kernel<<<BS_, 128>>>(x, g1 + l * E_, b1 + l * E_, xn);

        // fused QKV: [4096,384] @ [384,1344]
        gemm(true, xn, wqkv + (ll)l * E_ * QLD_, bqkv + (ll)l * QLD_, qkv,
             BS_, QLD_, QLD_, E_, E_, QLD_, QLD_,
             1, 1, 0, 0, 0, 0, 0, 0, 1.f, 0);

        // scores: z=(b,h); q at col h*192, k at h*192+64, K=64 (zero-padded)
        gemm(false, qkv, qkv + 64, nullptr, attn,
             S_, S_, S_, 64, QLD_, QLD_, S_,
             B_ * H_, H_,
             (ll)S_ * QLD_, HB_, (ll)S_ * QLD_, HB_,
             (ll)H_ * S_ * S_, (ll)S_ * S_,
             scale, FLAG_TRANSB);

        {
            dim3 blk(32, 8);
            softmax_causal<<<(B_ * H_ * S_) / 8, blk>>>(attn);
        }

        // PV -> concat layout
        gemm(false, attn, qkv + 128, nullptr, ocat,
             S_, D_, 54, S_, S_, QLD_, HD_,
             B_ * H_, H_,
             (ll)H_ * S_ * S_, (ll)S_ * S_, (ll)S_ * QLD_, HB_,
             (ll)S_ * HD_, D_,
             1.f, 0);

        // x += ocat @ Wc + bc
        gemm(false, ocat, Wc + (ll)l * HD_ * E_, bc + l * E_, x,
             BS_, E_, E_, HD_, HD_, E_, E_,
             1, 1, 0, 0, 0, 0, 0, 0, 1.f, FLAG_ACC);

        ln_kernel<<<BS_, 128>>>(x, g2 + l * E_, b2 + l * E_, xn);

        // h = gelu(xn @ W1 + bf1)
        gemm(true, xn, W1 + (ll)l * E_ * FF_, bf1 + (ll)l * FF_, hbuf,
             BS_, FF_, FF_, E_, E_, FF_, FF_,
             1, 1, 0, 0, 0, 0, 0, 0, 1.f, FLAG_GELU);

        // x += h @ W2 + bf2
        gemm(false, hbuf, W2 + (ll)l * FF_ * E_, bf2 + l * E_, x,
             BS_, E_, E_, FF_, FF_, E_, E_,
             1, 1, 0, 0, 0, 0, 0, 0, 1.f, FLAG_ACC);
    }

    ln_kernel<<<BS_, 128>>>(x, gf, bfin, xn);
    gemm(true, xn, Wout, bout, out,
         BS_, V_, V_, E_, E_, V_, V_,
         1, 1, 0, 0, 0, 0, 0, 0, 1.f, 0);

    const ll NLOG = (ll)BS_ * V_;
    if ((ll)out_size > NLOG) {
        zero_loss<<<1, 1>>>(lossp);
        loss_kernel<<<BS_, 256>>>(out, targets, lossp);
        fin_loss<<<1, 1>>>(lossp, out + NLOG);
    }
}

// round 11
// speedup vs baseline: 1.2277x; 1.1163x over previous
#include <cuda_runtime.h>
#include <math.h>
#include <stdint.h>

// ---------------- problem constants ----------------
constexpr int B_  = 8;
constexpr int S_  = 512;
constexpr int E_  = 384;
constexpr int H_  = 7;
constexpr int D_  = 54;
constexpr int L_  = 7;
constexpr int V_  = 32000;
constexpr int FF_ = 6 * E_;          // 2304
constexpr int BS_ = B_ * S_;         // 4096
constexpr int HD_ = H_ * D_;         // 378
constexpr int HB_ = 192;             // padded head block: q(64)|k(64)|v(64)
constexpr int QLD_ = H_ * HB_;       // 1344
constexpr float EPS_ = 1e-5f;

typedef long long ll;

// ---------------- scratch ----------------
__device__ float g_x   [BS_ * E_];
__device__ float g_xn  [BS_ * E_];
__device__ float g_qkv [BS_ * QLD_];
__device__ float g_wqkv[L_ * E_ * QLD_];
__device__ float g_bqkv[L_ * QLD_];
__device__ float g_ocat[BS_ * HD_];
__device__ float g_h   [BS_ * FF_];
__device__ float g_loss;

#define FLAG_TRANSB 1
#define FLAG_ACC    2
#define FLAG_GELU   4

__device__ __forceinline__ float gelu_f(float x) {
    return 0.5f * x * (1.0f + erff(x * 0.70710678118654752f));
}
__device__ __forceinline__ uint32_t f2tf32(float x) {
    uint32_t r;
    asm("cvt.rna.tf32.f32 %0, %1;" : "=r"(r) : "f"(x));
    return r;
}
#define MMA_TF32(ACC, A0, A1, A2, A3, B0, B1)                                  \
    asm volatile(                                                              \
        "mma.sync.aligned.m16n8k8.row.col.f32.tf32.tf32.f32 "                  \
        "{%0,%1,%2,%3}, {%4,%5,%6,%7}, {%8,%9}, {%0,%1,%2,%3};"                \
        : "+f"((ACC)[0]), "+f"((ACC)[1]), "+f"((ACC)[2]), "+f"((ACC)[3])       \
        : "r"(A0), "r"(A1), "r"(A2), "r"(A3), "r"(B0), "r"(B1))

// =====================================================================
// tf32 mma.sync GEMM (unchanged from R10)
// =====================================================================
template<int BM, int NT>
__global__ void __launch_bounds__(256, 1)
tc_gemm(const float* __restrict__ A, const float* __restrict__ Bm,
        const float* __restrict__ bias, float* __restrict__ C,
        int M, int N, int Nb, int K,
        int lda, int ldb, int ldc, int zdiv,
        ll sA1, ll sA2, ll sB1, ll sB2, ll sC1, ll sC2,
        float alpha, int flags)
{
    constexpr int BK = 16;
    constexpr int BN = 128;
    constexpr int MWARPS = BM / 64;
    constexpr int ASTR = BM + 4;
    constexpr int BSTR = BN + 4;
    constexpr int AW = BK * ASTR;
    constexpr int BW = BK * BSTR;
    constexpr int AE = BM / 16;
    constexpr int AE4 = BM / 64;

    extern __shared__ uint32_t sm[];

    {
        const int z = blockIdx.z;
        const int zq = z / zdiv, zr = z - zq * zdiv;
        A  += (ll)zq * sA1 + (ll)zr * sA2;
        Bm += (ll)zq * sB1 + (ll)zr * sB2;
        C  += (ll)zq * sC1 + (ll)zr * sC2;
    }

    const int row0 = blockIdx.y * BM;
    const int col0 = blockIdx.x * BN;
    const int tid  = threadIdx.x;
    const int warp = tid >> 5;
    const int lane = tid & 31;
    const int wm = (warp % MWARPS) * 64;
    const int wn = (warp / MWARPS) * (NT * 8);
    const int lr = lane >> 2;
    const int lc = lane & 3;
    const bool transB = (flags & FLAG_TRANSB);
    const bool a4 = ((lda & 3) == 0);
    const bool b4 = ((ldb & 3) == 0);
    const bool nfull = (col0 + BN <= Nb);

    float acc[4][NT][4];
#pragma unroll
    for (int mt = 0; mt < 4; mt++)
#pragma unroll
        for (int nt = 0; nt < NT; nt++)
#pragma unroll
            for (int c = 0; c < 4; c++) acc[mt][nt][c] = 0.f;

    float aR[AE], bR[8];
    const int nk = (K + BK - 1) / BK;

    auto loadA = [&](int k0) {
        if (a4 && (k0 + BK <= K)) {
#pragma unroll
            for (int i = 0; i < AE4; i++) {
                int e = tid + i * 256;
                int m = e >> 2, kq = e & 3;
                float4 v = *reinterpret_cast<const float4*>(
                    A + (ll)(row0 + m) * lda + k0 + kq * 4);
                aR[i*4+0] = v.x; aR[i*4+1] = v.y; aR[i*4+2] = v.z; aR[i*4+3] = v.w;
            }
        } else {
#pragma unroll
            for (int i = 0; i < AE; i++) {
                int e = tid + i * 256;
                int m = e >> 4, k = e & 15;
                aR[i] = (k0 + k < K) ? A[(ll)(row0 + m) * lda + k0 + k] : 0.f;
            }
        }
    };
    auto stsA = [&](int k0, uint32_t* As) {
        if (a4 && (k0 + BK <= K)) {
#pragma unroll
            for (int i = 0; i < AE4; i++) {
                int e = tid + i * 256;
                int m = e >> 2, kq = e & 3;
#pragma unroll
                for (int j = 0; j < 4; j++)
                    As[(kq * 4 + j) * ASTR + m] = f2tf32(aR[i*4+j]);
            }
        } else {
#pragma unroll
            for (int i = 0; i < AE; i++) {
                int e = tid + i * 256;
                int m = e >> 4, k = e & 15;
                As[k * ASTR + m] = f2tf32(aR[i]);
            }
        }
    };
    auto loadB = [&](int k0) {
        const bool kf = (k0 + BK <= K);
        if (transB) {
            if (kf && nfull && b4) {
#pragma unroll
                for (int i = 0; i < 2; i++) {
                    int e = tid + i * 256;
                    int n = e >> 2, kq = e & 3;
                    float4 v = *reinterpret_cast<const float4*>(
                        Bm + (ll)(col0 + n) * ldb + k0 + kq * 4);
                    bR[i*4+0] = v.x; bR[i*4+1] = v.y; bR[i*4+2] = v.z; bR[i*4+3] = v.w;
                }
            } else {
#pragma unroll
                for (int i = 0; i < 8; i++) {
                    int e = tid + i * 256;
                    int n = e >> 4, k = e & 15;
                    bR[i] = (col0 + n < Nb && k0 + k < K)
                          ? Bm[(ll)(col0 + n) * ldb + k0 + k] : 0.f;
                }
            }
        } else {
            if (kf && nfull && b4) {
#pragma unroll
                for (int i = 0; i < 2; i++) {
                    int e = tid + i * 256;
                    int k = e >> 5, n4 = (e & 31) << 2;
                    float4 v = *reinterpret_cast<const float4*>(
                        Bm + (ll)(k0 + k) * ldb + col0 + n4);
                    bR[i*4+0] = v.x; bR[i*4+1] = v.y; bR[i*4+2] = v.z; bR[i*4+3] = v.w;
                }
            } else {
#pragma unroll
                for (int i = 0; i < 8; i++) {
                    int e = tid + i * 256;
                    int k = e >> 7, n = e & 127;
                    bR[i] = (k0 + k < K && col0 + n < Nb)
                          ? Bm[(ll)(k0 + k) * ldb + col0 + n] : 0.f;
                }
            }
        }
    };
    auto stsB = [&](int k0, uint32_t* Bs) {
        const bool kf = (k0 + BK <= K);
        if (transB) {
            if (kf && nfull && b4) {
#pragma unroll
                for (int i = 0; i < 2; i++) {
                    int e = tid + i * 256;
                    int n = e >> 2, kq = e & 3;
#pragma unroll
                    for (int j = 0; j < 4; j++)
                        Bs[(kq * 4 + j) * BSTR + n] = f2tf32(bR[i*4+j]);
                }
            } else {
#pragma unroll
                for (int i = 0; i < 8; i++) {
                    int e = tid + i * 256;
                    int n = e >> 4, k = e & 15;
                    Bs[k * BSTR + n] = f2tf32(bR[i]);
                }
            }
        } else {
            if (kf && nfull && b4) {
#pragma unroll
                for (int i = 0; i < 2; i++) {
                    int e = tid + i * 256;
                    int k = e >> 5, n4 = (e & 31) << 2;
                    uint4 w;
                    w.x = f2tf32(bR[i*4+0]); w.y = f2tf32(bR[i*4+1]);
                    w.z = f2tf32(bR[i*4+2]); w.w = f2tf32(bR[i*4+3]);
                    *reinterpret_cast<uint4*>(&Bs[k * BSTR + n4]) = w;
                }
            } else {
#pragma unroll
                for (int i = 0; i < 8; i++) {
                    int e = tid + i * 256;
                    int k = e >> 7, n = e & 127;
                    Bs[k * BSTR + n] = f2tf32(bR[i]);
                }
            }
        }
    };

    loadA(0); loadB(0);
    stsA(0, sm); stsB(0, sm + AW);
    __syncthreads();

    int buf = 0;
    for (int it = 0; it < nk; it++) {
        if (it + 1 < nk) { loadA((it + 1) * BK); loadB((it + 1) * BK); }

        const uint32_t* As = sm + buf * (AW + BW);
        const uint32_t* Bs = As + AW;

#pragma unroll
        for (int ks = 0; ks < 2; ks++) {
            const int kk = ks * 8;
            uint32_t af[4][4], bf[NT][2];
#pragma unroll
            for (int mt = 0; mt < 4; mt++) {
                int m0 = wm + mt * 16 + lr;
                af[mt][0] = As[(kk + lc) * ASTR + m0];
                af[mt][1] = As[(kk + lc) * ASTR + m0 + 8];
                af[mt][2] = As[(kk + lc + 4) * ASTR + m0];
                af[mt][3] = As[(kk + lc + 4) * ASTR + m0 + 8];
            }
#pragma unroll
            for (int nt = 0; nt < NT; nt++) {
                int n0 = wn + nt * 8 + lr;
                bf[nt][0] = Bs[(kk + lc) * BSTR + n0];
                bf[nt][1] = Bs[(kk + lc + 4) * BSTR + n0];
            }
#pragma unroll
            for (int mt = 0; mt < 4; mt++)
#pragma unroll
                for (int nt = 0; nt < NT; nt++)
                    MMA_TF32(acc[mt][nt], af[mt][0], af[mt][1], af[mt][2], af[mt][3],
                             bf[nt][0], bf[nt][1]);
        }

        if (it + 1 < nk) {
            uint32_t* Asn = sm + (buf ^ 1) * (AW + BW);
            stsA((it + 1) * BK, Asn);
            stsB((it + 1) * BK, Asn + AW);
            __syncthreads();
            buf ^= 1;
        }
    }

    const bool doacc = (flags & FLAG_ACC);
    const bool dogel = (flags & FLAG_GELU);
#pragma unroll
    for (int mt = 0; mt < 4; mt++)
#pragma unroll
        for (int nt = 0; nt < NT; nt++) {
            int rb = row0 + wm + mt * 16 + lr;
            int cb = col0 + wn + nt * 8 + lc * 2;
#pragma unroll
            for (int h = 0; h < 2; h++) {
                int r = rb + h * 8;
                int c = cb;
                if (c >= N) continue;
                float v0 = acc[mt][nt][h * 2 + 0] * alpha;
                float v1 = acc[mt][nt][h * 2 + 1] * alpha;
                if (bias) {
                    v0 += bias[c];
                    if (c + 1 < N) v1 += bias[c + 1];
                }
                if (dogel) { v0 = gelu_f(v0); v1 = gelu_f(v1); }
                float* Cp = C + (ll)r * ldc + c;
                if (c + 1 < N) {
                    if (doacc) {
                        float2 o = *reinterpret_cast<const float2*>(Cp);
                        v0 += o.x; v1 += o.y;
                    }
                    *reinterpret_cast<float2*>(Cp) = make_float2(v0, v1);
                } else {
                    if (doacc) v0 += Cp[0];
                    Cp[0] = v0;
                }
            }
        }
}

// =====================================================================
// Fused causal flash attention (tf32 mma).
// Block = one (b, h, q-tile of 128). 8 warps / 256 threads.
// S-phase: warp w owns rows w*16..w*16+15 (full 128-col rows in-warp).
// PV-phase: warps 4x2 over O(128x64), per-row rescale via smem.
// =====================================================================
constexpr int QSTR_F = 132, KSTR_F = 132, VSTR_F = 68, PSTR_F = 132;
constexpr int OFF_Q = 0;                       // 64*132
constexpr int OFF_K = OFF_Q + 64 * QSTR_F;     // 8448
constexpr int OFF_V = OFF_K + 64 * KSTR_F;     // 16896 (128*68)
constexpr int OFF_P = OFF_V + 128 * VSTR_F;    // 25600 (128*132)
constexpr int OFF_SC = OFF_P + 128 * PSTR_F;   // 42496
constexpr int OFF_L  = OFF_SC + 128;           // 42624
constexpr int FLASH_WORDS = OFF_L + 128;       // 42752 -> 171008 B

__global__ void __launch_bounds__(256, 1)
flash_kernel(const float* __restrict__ qkv, float* __restrict__ ocat)
{
    extern __shared__ uint32_t fs[];
    float* fsf = reinterpret_cast<float*>(fs);

    const int qt = (int)gridDim.x - 1 - (int)blockIdx.x;   // heavy tiles first
    const int z = blockIdx.y;
    const int b = z / H_, h = z % H_;
    const ll browq = (ll)b * S_ + (ll)qt * 128;
    const int tid = threadIdx.x;
    const int warp = tid >> 5, lane = tid & 31;
    const int lr = lane >> 2, lc = lane & 3;
    const float scale = rsqrtf((float)D_);

    // ---- load Q tile (pre-scaled) into sQ [k][m] ----
    {
        const float* qp = qkv + browq * QLD_ + h * HB_;
#pragma unroll
        for (int i = 0; i < 8; i++) {
            int e = tid + i * 256;
            int m = e >> 4, kq = e & 15;
            float4 v = *reinterpret_cast<const float4*>(qp + (ll)m * QLD_ + kq * 4);
            uint32_t* dst = fs + OFF_Q + m;
            dst[(kq * 4 + 0) * QSTR_F] = f2tf32(v.x * scale);
            dst[(kq * 4 + 1) * QSTR_F] = f2tf32(v.y * scale);
            dst[(kq * 4 + 2) * QSTR_F] = f2tf32(v.z * scale);
            dst[(kq * 4 + 3) * QSTR_F] = f2tf32(v.w * scale);
        }
    }

    float oacc[2][4][4];
#pragma unroll
    for (int mt = 0; mt < 2; mt++)
#pragma unroll
        for (int nt = 0; nt < 4; nt++)
#pragma unroll
            for (int c = 0; c < 4; c++) oacc[mt][nt][c] = 0.f;

    const int owm = (warp & 3) * 32, own = (warp >> 2) * 32;
    const int swm = warp * 16;
    float mrow0 = -1e30f, mrow1 = -1e30f;
    float lrow0 = 0.f, lrow1 = 0.f;

    for (int kt = 0; kt <= qt; kt++) {
        const ll browk = (ll)b * S_ + (ll)kt * 128;
        // ---- stage K,V tiles ----
        {
            const float* kp = qkv + browk * QLD_ + h * HB_ + 64;
#pragma unroll
            for (int i = 0; i < 8; i++) {
                int e = tid + i * 256;
                int n = e >> 4, kq = e & 15;
                float4 v = *reinterpret_cast<const float4*>(kp + (ll)n * QLD_ + kq * 4);
                uint32_t* dst = fs + OFF_K + n;
                dst[(kq * 4 + 0) * KSTR_F] = f2tf32(v.x);
                dst[(kq * 4 + 1) * KSTR_F] = f2tf32(v.y);
                dst[(kq * 4 + 2) * KSTR_F] = f2tf32(v.z);
                dst[(kq * 4 + 3) * KSTR_F] = f2tf32(v.w);
            }
            const float* vp = qkv + browk * QLD_ + h * HB_ + 128;
#pragma unroll
            for (int i = 0; i < 8; i++) {
                int e = tid + i * 256;
                int kk2 = e >> 4, dq = e & 15;
                float4 v = *reinterpret_cast<const float4*>(vp + (ll)kk2 * QLD_ + dq * 4);
                uint32_t* dst = fs + OFF_V + kk2 * VSTR_F + dq * 4;
                dst[0] = f2tf32(v.x);
                dst[1] = f2tf32(v.y);
                dst[2] = f2tf32(v.z);
                dst[3] = f2tf32(v.w);
            }
        }
        __syncthreads();

        // ---- S = Q K^T for rows swm..swm+15 (full 128 cols in-warp) ----
        float s[16][4];
#pragma unroll
        for (int nt = 0; nt < 16; nt++)
#pragma unroll
            for (int c = 0; c < 4; c++) s[nt][c] = 0.f;

#pragma unroll
        for (int ks = 0; ks < 8; ks++) {
            const int kk = ks * 8;
            uint32_t a0 = fs[OFF_Q + (kk + lc) * QSTR_F + swm + lr];
            uint32_t a1 = fs[OFF_Q + (kk + lc) * QSTR_F + swm + lr + 8];
            uint32_t a2 = fs[OFF_Q + (kk + lc + 4) * QSTR_F + swm + lr];
            uint32_t a3 = fs[OFF_Q + (kk + lc + 4) * QSTR_F + swm + lr + 8];
#pragma unroll
            for (int nt = 0; nt < 16; nt++) {
                uint32_t b0 = fs[OFF_K + (kk + lc) * KSTR_F + nt * 8 + lr];
                uint32_t b1 = fs[OFF_K + (kk + lc + 4) * KSTR_F + nt * 8 + lr];
                MMA_TF32(s[nt], a0, a1, a2, a3, b0, b1);
            }
        }

        // ---- causal mask on the diagonal tile ----
        if (kt == qt) {
#pragma unroll
            for (int nt = 0; nt < 16; nt++) {
                int c0 = nt * 8 + 2 * lc;
                int r0 = swm + lr, r1 = r0 + 8;
                if (c0 > r0)     s[nt][0] = -1e30f;
                if (c0 + 1 > r0) s[nt][1] = -1e30f;
                if (c0 > r1)     s[nt][2] = -1e30f;
                if (c0 + 1 > r1) s[nt][3] = -1e30f;
            }
        }

        // ---- online softmax (2 rows per thread, quad-reduce) ----
        float mx0 = -1e30f, mx1 = -1e30f;
#pragma unroll
        for (int nt = 0; nt < 16; nt++) {
            mx0 = fmaxf(mx0, fmaxf(s[nt][0], s[nt][1]));
            mx1 = fmaxf(mx1, fmaxf(s[nt][2], s[nt][3]));
        }
        mx0 = fmaxf(mx0, __shfl_xor_sync(0xffffffffu, mx0, 1));
        mx0 = fmaxf(mx0, __shfl_xor_sync(0xffffffffu, mx0, 2));
        mx1 = fmaxf(mx1, __shfl_xor_sync(0xffffffffu, mx1, 1));
        mx1 = fmaxf(mx1, __shfl_xor_sync(0xffffffffu, mx1, 2));
        float mn0 = fmaxf(mrow0, mx0), mn1 = fmaxf(mrow1, mx1);
        float sc0 = __expf(mrow0 - mn0), sc1 = __expf(mrow1 - mn1);

        float sum0 = 0.f, sum1 = 0.f;
#pragma unroll
        for (int nt = 0; nt < 16; nt++) {
            float p00 = __expf(s[nt][0] - mn0);
            float p01 = __expf(s[nt][1] - mn0);
            float p10 = __expf(s[nt][2] - mn1);
            float p11 = __expf(s[nt][3] - mn1);
            sum0 += p00 + p01;
            sum1 += p10 + p11;
            const int key = nt * 8 + 2 * lc;
            fs[OFF_P + (key + 0) * PSTR_F + swm + lr]     = f2tf32(p00);
            fs[OFF_P + (key + 1) * PSTR_F + swm + lr]     = f2tf32(p01);
            fs[OFF_P + (key + 0) * PSTR_F + swm + lr + 8] = f2tf32(p10);
            fs[OFF_P + (key + 1) * PSTR_F + swm + lr + 8] = f2tf32(p11);
        }
        sum0 += __shfl_xor_sync(0xffffffffu, sum0, 1);
        sum0 += __shfl_xor_sync(0xffffffffu, sum0, 2);
        sum1 += __shfl_xor_sync(0xffffffffu, sum1, 1);
        sum1 += __shfl_xor_sync(0xffffffffu, sum1, 2);
        lrow0 = lrow0 * sc0 + sum0;
        lrow1 = lrow1 * sc1 + sum1;
        mrow0 = mn0; mrow1 = mn1;
        if (lc == 0) {
            fsf[OFF_SC + swm + lr]     = sc0;
            fsf[OFF_SC + swm + lr + 8] = sc1;
        }
        __syncthreads();

        // ---- O rescale + PV mma (warps 4x2 over O 128x64) ----
        float rs[2][2];
        rs[0][0] = fsf[OFF_SC + owm + lr];
        rs[0][1] = fsf[OFF_SC + owm + lr + 8];
        rs[1][0] = fsf[OFF_SC + owm + 16 + lr];
        rs[1][1] = fsf[OFF_SC + owm + 16 + lr + 8];
#pragma unroll
        for (int mt = 0; mt < 2; mt++)
#pragma unroll
            for (int nt = 0; nt < 4; nt++) {
                oacc[mt][nt][0] *= rs[mt][0];
                oacc[mt][nt][1] *= rs[mt][0];
                oacc[mt][nt][2] *= rs[mt][1];
                oacc[mt][nt][3] *= rs[mt][1];
            }
#pragma unroll
        for (int ks = 0; ks < 16; ks++) {
            const int kk = ks * 8;
            uint32_t a[2][4];
#pragma unroll
            for (int mt = 0; mt < 2; mt++) {
                int m0 = owm + mt * 16 + lr;
                a[mt][0] = fs[OFF_P + (kk + lc) * PSTR_F + m0];
                a[mt][1] = fs[OFF_P + (kk + lc) * PSTR_F + m0 + 8];
                a[mt][2] = fs[OFF_P + (kk + lc + 4) * PSTR_F + m0];
                a[mt][3] = fs[OFF_P + (kk + lc + 4) * PSTR_F + m0 + 8];
            }
#pragma unroll
            for (int nt = 0; nt < 4; nt++) {
                uint32_t b0 = fs[OFF_V + (kk + lc) * VSTR_F + own + nt * 8 + lr];
                uint32_t b1 = fs[OFF_V + (kk + lc + 4) * VSTR_F + own + nt * 8 + lr];
#pragma unroll
                for (int mt = 0; mt < 2; mt++)
                    MMA_TF32(oacc[mt][nt], a[mt][0], a[mt][1], a[mt][2], a[mt][3], b0, b1);
            }
        }
        __syncthreads();
    }

    // ---- normalize and write out ----
    if (lc == 0) {
        fsf[OFF_L + swm + lr]     = 1.f / lrow0;
        fsf[OFF_L + swm + lr + 8] = 1.f / lrow1;
    }
    __syncthreads();
    float il[2][2];
    il[0][0] = fsf[OFF_L + owm + lr];
    il[0][1] = fsf[OFF_L + owm + lr + 8];
    il[1][0] = fsf[OFF_L + owm + 16 + lr];
    il[1][1] = fsf[OFF_L + owm + 16 + lr + 8];

#pragma unroll
    for (int mt = 0; mt < 2; mt++)
#pragma unroll
        for (int nt = 0; nt < 4; nt++) {
            int d = own + nt * 8 + 2 * lc;
#pragma unroll
            for (int hf = 0; hf < 2; hf++) {
                int r = owm + mt * 16 + lr + hf * 8;
                float v0 = oacc[mt][nt][hf * 2 + 0] * il[mt][hf];
                float v1 = oacc[mt][nt][hf * 2 + 1] * il[mt][hf];
                float* orow = ocat + (browq + r) * HD_ + h * D_;
                if (d < D_)     orow[d] = v0;
                if (d + 1 < D_) orow[d + 1] = v1;
            }
        }
}

// ---------------- weight repack ----------------
__global__ void repack_qkv(const float* __restrict__ Wq, const float* __restrict__ Wk,
                           const float* __restrict__ Wv, float* __restrict__ Wp)
{
    ll idx = (ll)blockIdx.x * 256 + threadIdx.x;
    const ll total = (ll)L_ * E_ * QLD_;
    if (idx >= total) return;
    int c = (int)(idx % QLD_);
    ll le = idx / QLD_;
    int e = (int)(le % E_);
    int l = (int)(le / E_);
    int h = c / HB_, r = c % HB_, s = r >> 6, d = r & 63;
    float v = 0.f;
    if (d < D_) {
        const float* W = (s == 0) ? Wq : (s == 1) ? Wk : Wv;
        v = W[(((ll)l * H_ + h) * E_ + e) * D_ + d];
    }
    Wp[idx] = v;
}
__global__ void repack_bias(const float* __restrict__ bq, const float* __restrict__ bk,
                            const float* __restrict__ bv, float* __restrict__ bp)
{
    int idx = blockIdx.x * 256 + threadIdx.x;
    if (idx >= L_ * QLD_) return;
    int c = idx % QLD_, l = idx / QLD_;
    int h = c / HB_, r = c % HB_, s = r >> 6, d = r & 63;
    float v = 0.f;
    if (d < D_) {
        const float* bb = (s == 0) ? bq : (s == 1) ? bk : bv;
        v = bb[((ll)l * H_ + h) * D_ + d];
    }
    bp[idx] = v;
}

// ---------------- pointwise / reductions ----------------
__global__ void embed_kernel(const int* __restrict__ ids,
                             const float* __restrict__ tok,
                             const float* __restrict__ pos,
                             float* __restrict__ x)
{
    int row = blockIdx.x;
    int s = row % S_;
    ll id = ids[row];
    float* xr = x + (ll)row * E_;
    const float* tr = tok + id * E_;
    const float* pr = pos + (ll)s * E_;
    for (int i = threadIdx.x; i < E_; i += blockDim.x)
        xr[i] = tr[i] + pr[i];
}

__global__ void ln_kernel(const float* __restrict__ x,
                          const float* __restrict__ g,
                          const float* __restrict__ b,
                          float* __restrict__ y)
{
    int row = blockIdx.x;
    const float* xr = x + (ll)row * E_;
    float s = 0.f, ss = 0.f;
    for (int i = threadIdx.x; i < E_; i += 128) {
        float v = xr[i];
        s += v; ss += v * v;
    }
#pragma unroll
    for (int o = 16; o > 0; o >>= 1) {
        s  += __shfl_xor_sync(0xffffffffu, s, o);
        ss += __shfl_xor_sync(0xffffffffu, ss, o);
    }
    __shared__ float sh_s[4], sh_ss[4];
    int w = threadIdx.x >> 5;
    if ((threadIdx.x & 31) == 0) { sh_s[w] = s; sh_ss[w] = ss; }
    __syncthreads();
    s  = sh_s[0] + sh_s[1] + sh_s[2] + sh_s[3];
    ss = sh_ss[0] + sh_ss[1] + sh_ss[2] + sh_ss[3];
    float mean = s / E_;
    float var  = ss / E_ - mean * mean;
    float rstd = rsqrtf(var + EPS_);
    float* yr = y + (ll)row * E_;
    for (int i = threadIdx.x; i < E_; i += 128)
        yr[i] = (xr[i] - mean) * rstd * g[i] + b[i];
}

__global__ void loss_kernel(const float* __restrict__ logits,
                            const int* __restrict__ tgt,
                            float* __restrict__ acc)
{
    int row = blockIdx.x;
    const float* p = logits + (ll)row * V_;
    __shared__ float sh[8];
    float mx = -1e30f;
    for (int j = threadIdx.x; j < V_; j += 256) mx = fmaxf(mx, p[j]);
#pragma unroll
    for (int o = 16; o > 0; o >>= 1) mx = fmaxf(mx, __shfl_xor_sync(0xffffffffu, mx, o));
    int w = threadIdx.x >> 5;
    if ((threadIdx.x & 31) == 0) sh[w] = mx;
    __syncthreads();
    mx = sh[0];
#pragma unroll
    for (int i = 1; i < 8; i++) mx = fmaxf(mx, sh[i]);
    __syncthreads();
    float sum = 0.f;
    for (int j = threadIdx.x; j < V_; j += 256) sum += expf(p[j] - mx);
#pragma unroll
    for (int o = 16; o > 0; o >>= 1) sum += __shfl_xor_sync(0xffffffffu, sum, o);
    if ((threadIdx.x & 31) == 0) sh[w] = sum;
    __syncthreads();
    if (threadIdx.x == 0) {
        float tot = 0.f;
#pragma unroll
        for (int i = 0; i < 8; i++) tot += sh[i];
        float lse = mx + logf(tot);
        atomicAdd(acc, p[tgt[row]] - lse);
    }
}

__global__ void zero_loss(float* a) { *a = 0.f; }
__global__ void fin_loss(const float* a, float* out) { *out = -(*a) / (float)BS_; }

// ---------------- host driver ----------------
constexpr int SMEM_BIG   = 2 * (16 * (256 + 4) + 16 * 132) * 4;
constexpr int SMEM_SMALL = 2 * (16 * (128 + 4) + 16 * 132) * 4;
constexpr int SMEM_FLASH = FLASH_WORDS * 4;   // 171008 B

static void gemm(bool big, const float* A, const float* Bm, const float* bias, float* C,
                 int M, int N, int Nb, int K, int lda, int ldb, int ldc,
                 int batch, int zdiv,
                 ll sA1, ll sA2, ll sB1, ll sB2, ll sC1, ll sC2,
                 float alpha, int flags)
{
    if (big) {
        dim3 grid((N + 127) / 128, M / 256, batch);
        tc_gemm<256, 8><<<grid, 256, SMEM_BIG>>>(
            A, Bm, bias, C, M, N, Nb, K, lda, ldb, ldc,
            zdiv, sA1, sA2, sB1, sB2, sC1, sC2, alpha, flags);
    } else {
        dim3 grid((N + 127) / 128, M / 128, batch);
        tc_gemm<128, 4><<<grid, 256, SMEM_SMALL>>>(
            A, Bm, bias, C, M, N, Nb, K, lda, ldb, ldc,
            zdiv, sA1, sA2, sB1, sB2, sC1, sC2, alpha, flags);
    }
}

extern "C" void kernel_launch(void* const* d_in, const int* in_sizes, int n_in,
                              void* d_out, int out_size)
{
    const int*   input_ids = (const int*)d_in[0];
    const int*   targets   = (const int*)d_in[1];
    const float* tok_emb   = (const float*)d_in[2];
    const float* pos_emb   = (const float*)d_in[3];
    const float* Wq  = (const float*)d_in[4];
    const float* bq  = (const float*)d_in[5];
    const float* Wk  = (const float*)d_in[6];
    const float* bk  = (const float*)d_in[7];
    const float* Wv  = (const float*)d_in[8];
    const float* bv  = (const float*)d_in[9];
    const float* Wc  = (const float*)d_in[10];
    const float* bc  = (const float*)d_in[11];
    const float* g1  = (const float*)d_in[12];
    const float* b1  = (const float*)d_in[13];
    const float* g2  = (const float*)d_in[14];
    const float* b2  = (const float*)d_in[15];
    const float* W1  = (const float*)d_in[16];
    const float* bf1 = (const float*)d_in[17];
    const float* W2  = (const float*)d_in[18];
    const float* bf2 = (const float*)d_in[19];
    const float* gf   = (const float*)d_in[20];
    const float* bfin = (const float*)d_in[21];
    const float* Wout = (const float*)d_in[22];
    const float* bout = (const float*)d_in[23];
    float* out = (float*)d_out;

    cudaFuncSetAttribute(tc_gemm<256, 8>,
                         cudaFuncAttributeMaxDynamicSharedMemorySize, SMEM_BIG);
    cudaFuncSetAttribute(tc_gemm<128, 4>,
                         cudaFuncAttributeMaxDynamicSharedMemorySize, SMEM_SMALL);
    cudaFuncSetAttribute(flash_kernel,
                         cudaFuncAttributeMaxDynamicSharedMemorySize, SMEM_FLASH);

    float *x, *xn, *qkv, *wqkv, *bqkv, *ocat, *hbuf, *lossp;
    cudaGetSymbolAddress((void**)&x,    g_x);
    cudaGetSymbolAddress((void**)&xn,   g_xn);
    cudaGetSymbolAddress((void**)&qkv,  g_qkv);
    cudaGetSymbolAddress((void**)&wqkv, g_wqkv);
    cudaGetSymbolAddress((void**)&bqkv, g_bqkv);
    cudaGetSymbolAddress((void**)&ocat, g_ocat);
    cudaGetSymbolAddress((void**)&hbuf, g_h);
    cudaGetSymbolAddress((void**)&lossp, g_loss);

    {
        ll total = (ll)L_ * E_ * QLD_;
        repack_qkv<<<(int)((total + 255) / 256), 256>>>(Wq, Wk, Wv, wqkv);
        repack_bias<<<(L_ * QLD_ + 255) / 256, 256>>>(bq, bk, bv, bqkv);
    }

    embed_kernel<<<BS_, 128>>>(input_ids, tok_emb, pos_emb, x);

    for (int l = 0; l < L_; l++) {
        ln_kernel<<<BS_, 128>>>(x, g1 + l * E_, b1 + l * E_, xn);

        // fused QKV: [4096,384] @ [384,1344]
        gemm(true, xn, wqkv + (ll)l * E_ * QLD_, bqkv + (ll)l * QLD_, qkv,
             BS_, QLD_, QLD_, E_, E_, QLD_, QLD_,
             1, 1, 0, 0, 0, 0, 0, 0, 1.f, 0);

        // fused causal attention -> ocat
        {
            dim3 grid(S_ / 128, B_ * H_);
            flash_kernel<<<grid, 256, SMEM_FLASH>>>(qkv, ocat);
        }

        // x += ocat @ Wc + bc
        gemm(false, ocat, Wc + (ll)l * HD_ * E_, bc + l * E_, x,
             BS_, E_, E_, HD_, HD_, E_, E_,
             1, 1, 0, 0, 0, 0, 0, 0, 1.f, FLAG_ACC);

        ln_kernel<<<BS_, 128>>>(x, g2 + l * E_, b2 + l * E_, xn);

        // h = gelu(xn @ W1 + bf1)
        gemm(true, xn, W1 + (ll)l * E_ * FF_, bf1 + (ll)l * FF_, hbuf,
             BS_, FF_, FF_, E_, E_, FF_, FF_,
             1, 1, 0, 0, 0, 0, 0, 0, 1.f, FLAG_GELU);

        // x += h @ W2 + bf2
        gemm(false, hbuf, W2 + (ll)l * FF_ * E_, bf2 + l * E_, x,
             BS_, E_, E_, FF_, FF_, E_, E_,
             1, 1, 0, 0, 0, 0, 0, 0, 1.f, FLAG_ACC);
    }

    ln_kernel<<<BS_, 128>>>(x, gf, bfin, xn);
    gemm(true, xn, Wout, bout, out,
         BS_, V_, V_, E_, E_, V_, V_,
         1, 1, 0, 0, 0, 0, 0, 0, 1.f, 0);

    const ll NLOG = (ll)BS_ * V_;
    if ((ll)out_size > NLOG) {
        zero_loss<<<1, 1>>>(lossp);
        loss_kernel<<<BS_, 256>>>(out, targets, lossp);
        fin_loss<<<1, 1>>>(lossp, out + NLOG);
    }
}

// round 12
// speedup vs baseline: 1.4757x; 1.2020x over previous
#include <cuda_runtime.h>
#include <math.h>
#include <stdint.h>

// ---------------- problem constants ----------------
constexpr int B_  = 8;
constexpr int S_  = 512;
constexpr int E_  = 384;
constexpr int H_  = 7;
constexpr int D_  = 54;
constexpr int L_  = 7;
constexpr int V_  = 32000;
constexpr int FF_ = 6 * E_;          // 2304
constexpr int BS_ = B_ * S_;         // 4096
constexpr int HD_ = H_ * D_;         // 378
constexpr int HDP_ = 384;            // padded ocat row width (cols 378..383 stay 0)
constexpr int HB_ = 192;             // padded head block: q(64)|k(64)|v(64)
constexpr int QLD_ = H_ * HB_;       // 1344
constexpr float EPS_ = 1e-5f;

typedef long long ll;

// ---------------- scratch ----------------
__device__ float g_x   [BS_ * E_];
__device__ float g_xn  [BS_ * E_];
__device__ float g_qkv [BS_ * QLD_];
__device__ float g_wqkv[L_ * E_ * QLD_];
__device__ float g_bqkv[L_ * QLD_];
__device__ float g_wc  [L_ * HDP_ * E_];   // zero-padded Wc
__device__ float g_ocat[BS_ * HDP_];       // pad cols zero-init, never written
__device__ float g_h   [BS_ * FF_];
__device__ float g_loss;

#define FLAG_ACC    2
#define FLAG_GELU   4

__device__ __forceinline__ float gelu_f(float x) {
    return 0.5f * x * (1.0f + erff(x * 0.70710678118654752f));
}
__device__ __forceinline__ uint32_t f2tf32(float x) {
    uint32_t r;
    asm("cvt.rna.tf32.f32 %0, %1;" : "=r"(r) : "f"(x));
    return r;
}
__device__ __forceinline__ uint32_t smem_u32(const void* p) {
    uint32_t a;
    asm("{ .reg .u64 t; cvta.to.shared.u64 t, %1; cvt.u32.u64 %0, t; }"
        : "=r"(a) : "l"(p));
    return a;
}
#define MMA_TF32(ACC, A0, A1, A2, A3, B0, B1)                                  \
    asm volatile(                                                              \
        "mma.sync.aligned.m16n8k8.row.col.f32.tf32.tf32.f32 "                  \
        "{%0,%1,%2,%3}, {%4,%5,%6,%7}, {%8,%9}, {%0,%1,%2,%3};"                \
        : "+f"((ACC)[0]), "+f"((ACC)[1]), "+f"((ACC)[2]), "+f"((ACC)[3])       \
        : "r"(A0), "r"(A1), "r"(A2), "r"(A3), "r"(B0), "r"(B1))
#define CP_ASYNC16(DST, SRC)                                                   \
    asm volatile("cp.async.cg.shared.global [%0], [%1], 16;"                   \
                 :: "r"(DST), "l"(SRC))
#define CP_ASYNC16Z(DST, SRC, BYTES)                                           \
    asm volatile("cp.async.cg.shared.global [%0], [%1], 16, %2;"               \
                 :: "r"(DST), "l"(SRC), "r"(BYTES))
#define CP_COMMIT() asm volatile("cp.async.commit_group;")
#define CP_WAIT2()  asm volatile("cp.async.wait_group 2;")

// =====================================================================
// tf32 mma.sync GEMM with 4-stage cp.async pipeline (raw fp32 in smem,
// tf32 conversion at fragment load). Requires: M%BM==0, K%16==0,
// lda%4==0, ldb%4==0. N-tail handled by cp.async zfill + epilogue bound.
//   big  : BM=256, warp tile 64x64 (NT=8)
//   small: BM=128, warp tile 64x32 (NT=4)
// =====================================================================
template<int BM, int NT>
__global__ void __launch_bounds__(256, 1)
tc_gemm(const float* __restrict__ A, const float* __restrict__ Bm,
        const float* __restrict__ bias, float* __restrict__ C,
        int M, int N, int K,
        int lda, int ldb, int ldc, int zdiv,
        ll sA1, ll sA2, ll sB1, ll sB2, ll sC1, ll sC2,
        float alpha, int flags)
{
    constexpr int MWARPS = BM / 64;
    constexpr int ASTR = 20;                   // [m][k] stride (bank-safe)
    constexpr int BSTR = 132;                  // [k][n] stride
    constexpr int AW = BM * ASTR;
    constexpr int SWORDS = AW + 16 * BSTR;
    constexpr int AE4 = BM / 64;               // A float4 per thread per stage

    extern __shared__ uint32_t sm[];

    {
        const int z = blockIdx.z;
        const int zq = z / zdiv, zr = z - zq * zdiv;
        A  += (ll)zq * sA1 + (ll)zr * sA2;
        Bm += (ll)zq * sB1 + (ll)zr * sB2;
        C  += (ll)zq * sC1 + (ll)zr * sC2;
    }

    const int row0 = blockIdx.y * BM;
    const int col0 = blockIdx.x * 128;
    const int tid  = threadIdx.x;
    const int warp = tid >> 5;
    const int lane = tid & 31;
    const int wm = (warp % MWARPS) * 64;
    const int wn = (warp / MWARPS) * (NT * 8);
    const int lr = lane >> 2;
    const int lc = lane & 3;

    float acc[4][NT][4];
#pragma unroll
    for (int mt = 0; mt < 4; mt++)
#pragma unroll
        for (int nt = 0; nt < NT; nt++)
#pragma unroll
            for (int c = 0; c < 4; c++) acc[mt][nt][c] = 0.f;

    const int nk = K >> 4;
    const uint32_t smBase = smem_u32(sm);

    auto issue = [&](int kt) {
        const int st = kt & 3;
        const uint32_t aBase = smBase + (uint32_t)st * SWORDS * 4;
        const uint32_t bBase = aBase + AW * 4;
        const int k0 = kt << 4;
#pragma unroll
        for (int i = 0; i < AE4; i++) {
            int e = tid + i * 256;
            int m = e >> 2, kq = e & 3;
            const float* src = A + (ll)(row0 + m) * lda + k0 + kq * 4;
            CP_ASYNC16(aBase + (uint32_t)(m * ASTR + kq * 4) * 4, src);
        }
#pragma unroll
        for (int i = 0; i < 2; i++) {
            int e = tid + i * 256;
            int k = e >> 5, n4 = (e & 31) << 2;
            const bool ok = (col0 + n4 < N);
            const float* src = ok ? (Bm + (ll)(k0 + k) * ldb + col0 + n4) : Bm;
            CP_ASYNC16Z(bBase + (uint32_t)(k * BSTR + n4) * 4, src, ok ? 16 : 0);
        }
    };

    issue(0); CP_COMMIT();
    issue(1); CP_COMMIT();
    issue(2); CP_COMMIT();

    for (int kt = 0; kt < nk; kt++) {
        CP_WAIT2();
        __syncthreads();
        if (kt + 3 < nk) issue(kt + 3);
        CP_COMMIT();

        const uint32_t* As = sm + (kt & 3) * SWORDS;
        const uint32_t* Bs = As + AW;

#pragma unroll
        for (int ks = 0; ks < 2; ks++) {
            const int kk = ks * 8;
            uint32_t af[4][4], bf[NT][2];
#pragma unroll
            for (int mt = 0; mt < 4; mt++) {
                const uint32_t* Ab = As + (wm + mt * 16 + lr) * ASTR + kk + lc;
                af[mt][0] = f2tf32(__uint_as_float(Ab[0]));
                af[mt][1] = f2tf32(__uint_as_float(Ab[8 * ASTR]));
                af[mt][2] = f2tf32(__uint_as_float(Ab[4]));
                af[mt][3] = f2tf32(__uint_as_float(Ab[8 * ASTR + 4]));
            }
#pragma unroll
            for (int nt = 0; nt < NT; nt++) {
                const int n0 = wn + nt * 8 + lr;
                bf[nt][0] = f2tf32(__uint_as_float(Bs[(kk + lc) * BSTR + n0]));
                bf[nt][1] = f2tf32(__uint_as_float(Bs[(kk + lc + 4) * BSTR + n0]));
            }
#pragma unroll
            for (int mt = 0; mt < 4; mt++)
#pragma unroll
                for (int nt = 0; nt < NT; nt++)
                    MMA_TF32(acc[mt][nt], af[mt][0], af[mt][1], af[mt][2], af[mt][3],
                             bf[nt][0], bf[nt][1]);
        }
    }

    // ---- epilogue ----
    const bool doacc = (flags & FLAG_ACC);
    const bool dogel = (flags & FLAG_GELU);
#pragma unroll
    for (int mt = 0; mt < 4; mt++)
#pragma unroll
        for (int nt = 0; nt < NT; nt++) {
            int rb = row0 + wm + mt * 16 + lr;
            int cb = col0 + wn + nt * 8 + lc * 2;
#pragma unroll
            for (int h = 0; h < 2; h++) {
                int r = rb + h * 8;
                int c = cb;
                if (c >= N) continue;
                float v0 = acc[mt][nt][h * 2 + 0] * alpha;
                float v1 = acc[mt][nt][h * 2 + 1] * alpha;
                if (bias) {
                    v0 += bias[c];
                    if (c + 1 < N) v1 += bias[c + 1];
                }
                if (dogel) { v0 = gelu_f(v0); v1 = gelu_f(v1); }
                float* Cp = C + (ll)r * ldc + c;
                if (c + 1 < N) {
                    if (doacc) {
                        float2 o = *reinterpret_cast<const float2*>(Cp);
                        v0 += o.x; v1 += o.y;
                    }
                    *reinterpret_cast<float2*>(Cp) = make_float2(v0, v1);
                } else {
                    if (doacc) v0 += Cp[0];
                    Cp[0] = v0;
                }
            }
        }
}

// =====================================================================
// Fused causal flash attention (unchanged except ocat stride 384)
// =====================================================================
constexpr int QSTR_F = 132, KSTR_F = 132, VSTR_F = 68, PSTR_F = 132;
constexpr int OFF_Q = 0;
constexpr int OFF_K = OFF_Q + 64 * QSTR_F;
constexpr int OFF_V = OFF_K + 64 * KSTR_F;
constexpr int OFF_P = OFF_V + 128 * VSTR_F;
constexpr int OFF_SC = OFF_P + 128 * PSTR_F;
constexpr int OFF_L  = OFF_SC + 128;
constexpr int FLASH_WORDS = OFF_L + 128;

__global__ void __launch_bounds__(256, 1)
flash_kernel(const float* __restrict__ qkv, float* __restrict__ ocat)
{
    extern __shared__ uint32_t fs[];
    float* fsf = reinterpret_cast<float*>(fs);

    const int qt = (int)gridDim.x - 1 - (int)blockIdx.x;
    const int z = blockIdx.y;
    const int b = z / H_, h = z % H_;
    const ll browq = (ll)b * S_ + (ll)qt * 128;
    const int tid = threadIdx.x;
    const int warp = tid >> 5, lane = tid & 31;
    const int lr = lane >> 2, lc = lane & 3;
    const float scale = rsqrtf((float)D_);

    {
        const float* qp = qkv + browq * QLD_ + h * HB_;
#pragma unroll
        for (int i = 0; i < 8; i++) {
            int e = tid + i * 256;
            int m = e >> 4, kq = e & 15;
            float4 v = *reinterpret_cast<const float4*>(qp + (ll)m * QLD_ + kq * 4);
            uint32_t* dst = fs + OFF_Q + m;
            dst[(kq * 4 + 0) * QSTR_F] = f2tf32(v.x * scale);
            dst[(kq * 4 + 1) * QSTR_F] = f2tf32(v.y * scale);
            dst[(kq * 4 + 2) * QSTR_F] = f2tf32(v.z * scale);
            dst[(kq * 4 + 3) * QSTR_F] = f2tf32(v.w * scale);
        }
    }

    float oacc[2][4][4];
#pragma unroll
    for (int mt = 0; mt < 2; mt++)
#pragma unroll
        for (int nt = 0; nt < 4; nt++)
#pragma unroll
            for (int c = 0; c < 4; c++) oacc[mt][nt][c] = 0.f;

    const int owm = (warp & 3) * 32, own = (warp >> 2) * 32;
    const int swm = warp * 16;
    float mrow0 = -1e30f, mrow1 = -1e30f;
    float lrow0 = 0.f, lrow1 = 0.f;

    for (int kt = 0; kt <= qt; kt++) {
        const ll browk = (ll)b * S_ + (ll)kt * 128;
        {
            const float* kp = qkv + browk * QLD_ + h * HB_ + 64;
#pragma unroll
            for (int i = 0; i < 8; i++) {
                int e = tid + i * 256;
                int n = e >> 4, kq = e & 15;
                float4 v = *reinterpret_cast<const float4*>(kp + (ll)n * QLD_ + kq * 4);
                uint32_t* dst = fs + OFF_K + n;
                dst[(kq * 4 + 0) * KSTR_F] = f2tf32(v.x);
                dst[(kq * 4 + 1) * KSTR_F] = f2tf32(v.y);
                dst[(kq * 4 + 2) * KSTR_F] = f2tf32(v.z);
                dst[(kq * 4 + 3) * KSTR_F] = f2tf32(v.w);
            }
            const float* vp = qkv + browk * QLD_ + h * HB_ + 128;
#pragma unroll
            for (int i = 0; i < 8; i++) {
                int e = tid + i * 256;
                int kk2 = e >> 4, dq = e & 15;
                float4 v = *reinterpret_cast<const float4*>(vp + (ll)kk2 * QLD_ + dq * 4);
                uint32_t* dst = fs + OFF_V + kk2 * VSTR_F + dq * 4;
                dst[0] = f2tf32(v.x);
                dst[1] = f2tf32(v.y);
                dst[2] = f2tf32(v.z);
                dst[3] = f2tf32(v.w);
            }
        }
        __syncthreads();

        float s[16][4];
#pragma unroll
        for (int nt = 0; nt < 16; nt++)
#pragma unroll
            for (int c = 0; c < 4; c++) s[nt][c] = 0.f;

#pragma unroll
        for (int ks = 0; ks < 8; ks++) {
            const int kk = ks * 8;
            uint32_t a0 = fs[OFF_Q + (kk + lc) * QSTR_F + swm + lr];
            uint32_t a1 = fs[OFF_Q + (kk + lc) * QSTR_F + swm + lr + 8];
            uint32_t a2 = fs[OFF_Q + (kk + lc + 4) * QSTR_F + swm + lr];
            uint32_t a3 = fs[OFF_Q + (kk + lc + 4) * QSTR_F + swm + lr + 8];
#pragma unroll
            for (int nt = 0; nt < 16; nt++) {
                uint32_t b0 = fs[OFF_K + (kk + lc) * KSTR_F + nt * 8 + lr];
                uint32_t b1 = fs[OFF_K + (kk + lc + 4) * KSTR_F + nt * 8 + lr];
                MMA_TF32(s[nt], a0, a1, a2, a3, b0, b1);
            }
        }

        if (kt == qt) {
#pragma unroll
            for (int nt = 0; nt < 16; nt++) {
                int c0 = nt * 8 + 2 * lc;
                int r0 = swm + lr, r1 = r0 + 8;
                if (c0 > r0)     s[nt][0] = -1e30f;
                if (c0 + 1 > r0) s[nt][1] = -1e30f;
                if (c0 > r1)     s[nt][2] = -1e30f;
                if (c0 + 1 > r1) s[nt][3] = -1e30f;
            }
        }

        float mx0 = -1e30f, mx1 = -1e30f;
#pragma unroll
        for (int nt = 0; nt < 16; nt++) {
            mx0 = fmaxf(mx0, fmaxf(s[nt][0], s[nt][1]));
            mx1 = fmaxf(mx1, fmaxf(s[nt][2], s[nt][3]));
        }
        mx0 = fmaxf(mx0, __shfl_xor_sync(0xffffffffu, mx0, 1));
        mx0 = fmaxf(mx0, __shfl_xor_sync(0xffffffffu, mx0, 2));
        mx1 = fmaxf(mx1, __shfl_xor_sync(0xffffffffu, mx1, 1));
        mx1 = fmaxf(mx1, __shfl_xor_sync(0xffffffffu, mx1, 2));
        float mn0 = fmaxf(mrow0, mx0), mn1 = fmaxf(mrow1, mx1);
        float sc0 = __expf(mrow0 - mn0), sc1 = __expf(mrow1 - mn1);

        float sum0 = 0.f, sum1 = 0.f;
#pragma unroll
        for (int nt = 0; nt < 16; nt++) {
            float p00 = __expf(s[nt][0] - mn0);
            float p01 = __expf(s[nt][1] - mn0);
            float p10 = __expf(s[nt][2] - mn1);
            float p11 = __expf(s[nt][3] - mn1);
            sum0 += p00 + p01;
            sum1 += p10 + p11;
            const int key = nt * 8 + 2 * lc;
            fs[OFF_P + (key + 0) * PSTR_F + swm + lr]     = f2tf32(p00);
            fs[OFF_P + (key + 1) * PSTR_F + swm + lr]     = f2tf32(p01);
            fs[OFF_P + (key + 0) * PSTR_F + swm + lr + 8] = f2tf32(p10);
            fs[OFF_P + (key + 1) * PSTR_F + swm + lr + 8] = f2tf32(p11);
        }
        sum0 += __shfl_xor_sync(0xffffffffu, sum0, 1);
        sum0 += __shfl_xor_sync(0xffffffffu, sum0, 2);
        sum1 += __shfl_xor_sync(0xffffffffu, sum1, 1);
        sum1 += __shfl_xor_sync(0xffffffffu, sum1, 2);
        lrow0 = lrow0 * sc0 + sum0;
        lrow1 = lrow1 * sc1 + sum1;
        mrow0 = mn0; mrow1 = mn1;
        if (lc == 0) {
            fsf[OFF_SC + swm + lr]     = sc0;
            fsf[OFF_SC + swm + lr + 8] = sc1;
        }
        __syncthreads();

        float rs[2][2];
        rs[0][0] = fsf[OFF_SC + owm + lr];
        rs[0][1] = fsf[OFF_SC + owm + lr + 8];
        rs[1][0] = fsf[OFF_SC + owm + 16 + lr];
        rs[1][1] = fsf[OFF_SC + owm + 16 + lr + 8];
#pragma unroll
        for (int mt = 0; mt < 2; mt++)
#pragma unroll
            for (int nt = 0; nt < 4; nt++) {
                oacc[mt][nt][0] *= rs[mt][0];
                oacc[mt][nt][1] *= rs[mt][0];
                oacc[mt][nt][2] *= rs[mt][1];
                oacc[mt][nt][3] *= rs[mt][1];
            }
#pragma unroll
        for (int ks = 0; ks < 16; ks++) {
            const int kk = ks * 8;
            uint32_t a[2][4];
#pragma unroll
            for (int mt = 0; mt < 2; mt++) {
                int m0 = owm + mt * 16 + lr;
                a[mt][0] = fs[OFF_P + (kk + lc) * PSTR_F + m0];
                a[mt][1] = fs[OFF_P + (kk + lc) * PSTR_F + m0 + 8];
                a[mt][2] = fs[OFF_P + (kk + lc + 4) * PSTR_F + m0];
                a[mt][3] = fs[OFF_P + (kk + lc + 4) * PSTR_F + m0 + 8];
            }
#pragma unroll
            for (int nt = 0; nt < 4; nt++) {
                uint32_t b0 = fs[OFF_V + (kk + lc) * VSTR_F + own + nt * 8 + lr];
                uint32_t b1 = fs[OFF_V + (kk + lc + 4) * VSTR_F + own + nt * 8 + lr];
#pragma unroll
                for (int mt = 0; mt < 2; mt++)
                    MMA_TF32(oacc[mt][nt], a[mt][0], a[mt][1], a[mt][2], a[mt][3], b0, b1);
            }
        }
        __syncthreads();
    }

    if (lc == 0) {
        fsf[OFF_L + swm + lr]     = 1.f / lrow0;
        fsf[OFF_L + swm + lr + 8] = 1.f / lrow1;
    }
    __syncthreads();
    float il[2][2];
    il[0][0] = fsf[OFF_L + owm + lr];
    il[0][1] = fsf[OFF_L + owm + lr + 8];
    il[1][0] = fsf[OFF_L + owm + 16 + lr];
    il[1][1] = fsf[OFF_L + owm + 16 + lr + 8];

#pragma unroll
    for (int mt = 0; mt < 2; mt++)
#pragma unroll
        for (int nt = 0; nt < 4; nt++) {
            int d = own + nt * 8 + 2 * lc;
#pragma unroll
            for (int hf = 0; hf < 2; hf++) {
                int r = owm + mt * 16 + lr + hf * 8;
                float v0 = oacc[mt][nt][hf * 2 + 0] * il[mt][hf];
                float v1 = oacc[mt][nt][hf * 2 + 1] * il[mt][hf];
                float* orow = ocat + (browq + r) * HDP_ + h * D_;
                if (d < D_)     orow[d] = v0;
                if (d + 1 < D_) orow[d + 1] = v1;
            }
        }
}

// ---------------- weight repacks ----------------
__global__ void repack_qkv(const float* __restrict__ Wq, const float* __restrict__ Wk,
                           const float* __restrict__ Wv, float* __restrict__ Wp)
{
    ll idx = (ll)blockIdx.x * 256 + threadIdx.x;
    const ll total = (ll)L_ * E_ * QLD_;
    if (idx >= total) return;
    int c = (int)(idx % QLD_);
    ll le = idx / QLD_;
    int e = (int)(le % E_);
    int l = (int)(le / E_);
    int h = c / HB_, r = c % HB_, s = r >> 6, d = r & 63;
    float v = 0.f;
    if (d < D_) {
        const float* W = (s == 0) ? Wq : (s == 1) ? Wk : Wv;
        v = W[(((ll)l * H_ + h) * E_ + e) * D_ + d];
    }
    Wp[idx] = v;
}
__global__ void repack_bias(const float* __restrict__ bq, const float* __restrict__ bk,
                            const float* __restrict__ bv, float* __restrict__ bp)
{
    int idx = blockIdx.x * 256 + threadIdx.x;
    if (idx >= L_ * QLD_) return;
    int c = idx % QLD_, l = idx / QLD_;
    int h = c / HB_, r = c % HB_, s = r >> 6, d = r & 63;
    float v = 0.f;
    if (d < D_) {
        const float* bb = (s == 0) ? bq : (s == 1) ? bk : bv;
        v = bb[((ll)l * H_ + h) * D_ + d];
    }
    bp[idx] = v;
}
// Wc [L, 378, E] -> [L, 384, E] zero-padded rows
__global__ void repack_wc(const float* __restrict__ Wc, float* __restrict__ Wp)
{
    ll idx = (ll)blockIdx.x * 256 + threadIdx.x;
    const ll total = (ll)L_ * HDP_ * E_;
    if (idx >= total) return;
    int e = (int)(idx % E_);
    ll lr = idx / E_;
    int r = (int)(lr % HDP_);
    int l = (int)(lr / HDP_);
    Wp[idx] = (r < HD_) ? Wc[((ll)l * HD_ + r) * E_ + e] : 0.f;
}

// ---------------- pointwise / reductions ----------------
__global__ void embed_kernel(const int* __restrict__ ids,
                             const float* __restrict__ tok,
                             const float* __restrict__ pos,
                             float* __restrict__ x)
{
    int row = blockIdx.x;
    int s = row % S_;
    ll id = ids[row];
    float* xr = x + (ll)row * E_;
    const float* tr = tok + id * E_;
    const float* pr = pos + (ll)s * E_;
    for (int i = threadIdx.x; i < E_; i += blockDim.x)
        xr[i] = tr[i] + pr[i];
}

__global__ void ln_kernel(const float* __restrict__ x,
                          const float* __restrict__ g,
                          const float* __restrict__ b,
                          float* __restrict__ y)
{
    int row = blockIdx.x;
    const float* xr = x + (ll)row * E_;
    float s = 0.f, ss = 0.f;
    for (int i = threadIdx.x; i < E_; i += 128) {
        float v = xr[i];
        s += v; ss += v * v;
    }
#pragma unroll
    for (int o = 16; o > 0; o >>= 1) {
        s  += __shfl_xor_sync(0xffffffffu, s, o);
        ss += __shfl_xor_sync(0xffffffffu, ss, o);
    }
    __shared__ float sh_s[4], sh_ss[4];
    int w = threadIdx.x >> 5;
    if ((threadIdx.x & 31) == 0) { sh_s[w] = s; sh_ss[w] = ss; }
    __syncthreads();
    s  = sh_s[0] + sh_s[1] + sh_s[2] + sh_s[3];
    ss = sh_ss[0] + sh_ss[1] + sh_ss[2] + sh_ss[3];
    float mean = s / E_;
    float var  = ss / E_ - mean * mean;
    float rstd = rsqrtf(var + EPS_);
    float* yr = y + (ll)row * E_;
    for (int i = threadIdx.x; i < E_; i += 128)
        yr[i] = (xr[i] - mean) * rstd * g[i] + b[i];
}

__global__ void loss_kernel(const float* __restrict__ logits,
                            const int* __restrict__ tgt,
                            float* __restrict__ acc)
{
    int row = blockIdx.x;
    const float* p = logits + (ll)row * V_;
    __shared__ float sh[8];
    float mx = -1e30f;
    for (int j = threadIdx.x; j < V_; j += 256) mx = fmaxf(mx, p[j]);
#pragma unroll
    for (int o = 16; o > 0; o >>= 1) mx = fmaxf(mx, __shfl_xor_sync(0xffffffffu, mx, o));
    int w = threadIdx.x >> 5;
    if ((threadIdx.x & 31) == 0) sh[w] = mx;
    __syncthreads();
    mx = sh[0];
#pragma unroll
    for (int i = 1; i < 8; i++) mx = fmaxf(mx, sh[i]);
    __syncthreads();
    float sum = 0.f;
    for (int j = threadIdx.x; j < V_; j += 256) sum += expf(p[j] - mx);
#pragma unroll
    for (int o = 16; o > 0; o >>= 1) sum += __shfl_xor_sync(0xffffffffu, sum, o);
    if ((threadIdx.x & 31) == 0) sh[w] = sum;
    __syncthreads();
    if (threadIdx.x == 0) {
        float tot = 0.f;
#pragma unroll
        for (int i = 0; i < 8; i++) tot += sh[i];
        float lse = mx + logf(tot);
        atomicAdd(acc, p[tgt[row]] - lse);
    }
}

__global__ void zero_loss(float* a) { *a = 0.f; }
__global__ void fin_loss(const float* a, float* out) { *out = -(*a) / (float)BS_; }

// ---------------- host driver ----------------
constexpr int SMEM_BIG   = 4 * (256 * 20 + 16 * 132) * 4;   // 115712 B
constexpr int SMEM_SMALL = 4 * (128 * 20 + 16 * 132) * 4;   // 74752 B
constexpr int SMEM_FLASH = FLASH_WORDS * 4;

static void gemm(bool big, const float* A, const float* Bm, const float* bias, float* C,
                 int M, int N, int K, int lda, int ldb, int ldc,
                 int batch, int zdiv,
                 ll sA1, ll sA2, ll sB1, ll sB2, ll sC1, ll sC2,
                 float alpha, int flags)
{
    if (big) {
        dim3 grid((N + 127) / 128, M / 256, batch);
        tc_gemm<256, 8><<<grid, 256, SMEM_BIG>>>(
            A, Bm, bias, C, M, N, K, lda, ldb, ldc,
            zdiv, sA1, sA2, sB1, sB2, sC1, sC2, alpha, flags);
    } else {
        dim3 grid((N + 127) / 128, M / 128, batch);
        tc_gemm<128, 4><<<grid, 256, SMEM_SMALL>>>(
            A, Bm, bias, C, M, N, K, lda, ldb, ldc,
            zdiv, sA1, sA2, sB1, sB2, sC1, sC2, alpha, flags);
    }
}

extern "C" void kernel_launch(void* const* d_in, const int* in_sizes, int n_in,
                              void* d_out, int out_size)
{
    const int*   input_ids = (const int*)d_in[0];
    const int*   targets   = (const int*)d_in[1];
    const float* tok_emb   = (const float*)d_in[2];
    const float* pos_emb   = (const float*)d_in[3];
    const float* Wq  = (const float*)d_in[4];
    const float* bq  = (const float*)d_in[5];
    const float* Wk  = (const float*)d_in[6];
    const float* bk  = (const float*)d_in[7];
    const float* Wv  = (const float*)d_in[8];
    const float* bv  = (const float*)d_in[9];
    const float* Wc  = (const float*)d_in[10];
    const float* bc  = (const float*)d_in[11];
    const float* g1  = (const float*)d_in[12];
    const float* b1  = (const float*)d_in[13];
    const float* g2  = (const float*)d_in[14];
    const float* b2  = (const float*)d_in[15];
    const float* W1  = (const float*)d_in[16];
    const float* bf1 = (const float*)d_in[17];
    const float* W2  = (const float*)d_in[18];
    const float* bf2 = (const float*)d_in[19];
    const float* gf   = (const float*)d_in[20];
    const float* bfin = (const float*)d_in[21];
    const float* Wout = (const float*)d_in[22];
    const float* bout = (const float*)d_in[23];
    float* out = (float*)d_out;

    cudaFuncSetAttribute(tc_gemm<256, 8>,
                         cudaFuncAttributeMaxDynamicSharedMemorySize, SMEM_BIG);
    cudaFuncSetAttribute(tc_gemm<128, 4>,
                         cudaFuncAttributeMaxDynamicSharedMemorySize, SMEM_SMALL);
    cudaFuncSetAttribute(flash_kernel,
                         cudaFuncAttributeMaxDynamicSharedMemorySize, SMEM_FLASH);

    float *x, *xn, *qkv, *wqkv, *bqkv, *wcp, *ocat, *hbuf, *lossp;
    cudaGetSymbolAddress((void**)&x,    g_x);
    cudaGetSymbolAddress((void**)&xn,   g_xn);
    cudaGetSymbolAddress((void**)&qkv,  g_qkv);
    cudaGetSymbolAddress((void**)&wqkv, g_wqkv);
    cudaGetSymbolAddress((void**)&bqkv, g_bqkv);
    cudaGetSymbolAddress((void**)&wcp,  g_wc);
    cudaGetSymbolAddress((void**)&ocat, g_ocat);
    cudaGetSymbolAddress((void**)&hbuf, g_h);
    cudaGetSymbolAddress((void**)&lossp, g_loss);

    {
        ll total = (ll)L_ * E_ * QLD_;
        repack_qkv<<<(int)((total + 255) / 256), 256>>>(Wq, Wk, Wv, wqkv);
        repack_bias<<<(L_ * QLD_ + 255) / 256, 256>>>(bq, bk, bv, bqkv);
        ll tot2 = (ll)L_ * HDP_ * E_;
        repack_wc<<<(int)((tot2 + 255) / 256), 256>>>(Wc, wcp);
    }

    embed_kernel<<<BS_, 128>>>(input_ids, tok_emb, pos_emb, x);

    for (int l = 0; l < L_; l++) {
        ln_kernel<<<BS_, 128>>>(x, g1 + l * E_, b1 + l * E_, xn);

        // fused QKV: [4096,384] @ [384,1344]
        gemm(true, xn, wqkv + (ll)l * E_ * QLD_, bqkv + (ll)l * QLD_, qkv,
             BS_, QLD_, E_, E_, QLD_, QLD_,
             1, 1, 0, 0, 0, 0, 0, 0, 1.f, 0);

        // fused causal attention -> ocat (stride 384, pad cols stay 0)
        {
            dim3 grid(S_ / 128, B_ * H_);
            flash_kernel<<<grid, 256, SMEM_FLASH>>>(qkv, ocat);
        }

        // x += ocat @ Wc_pad + bc   (K padded 378->384)
        gemm(false, ocat, wcp + (ll)l * HDP_ * E_, bc + l * E_, x,
             BS_, E_, HDP_, HDP_, E_, E_,
             1, 1, 0, 0, 0, 0, 0, 0, 1.f, FLAG_ACC);

        ln_kernel<<<BS_, 128>>>(x, g2 + l * E_, b2 + l * E_, xn);

        // h = gelu(xn @ W1 + bf1)
        gemm(true, xn, W1 + (ll)l * E_ * FF_, bf1 + (ll)l * FF_, hbuf,
             BS_, FF_, E_, E_, FF_, FF_,
             1, 1, 0, 0, 0, 0, 0, 0, 1.f, FLAG_GELU);

        // x += h @ W2 + bf2
        gemm(false, hbuf, W2 + (ll)l * FF_ * E_, bf2 + l * E_, x,
             BS_, E_, FF_, FF_, E_, E_,
             1, 1, 0, 0, 0, 0, 0, 0, 1.f, FLAG_ACC);
    }

    ln_kernel<<<BS_, 128>>>(x, gf, bfin, xn);
    gemm(true, xn, Wout, bout, out,
         BS_, V_, E_, E_, V_, V_,
         1, 1, 0, 0, 0, 0, 0, 0, 1.f, 0);

    const ll NLOG = (ll)BS_ * V_;
    if ((ll)out_size > NLOG) {
        zero_loss<<<1, 1>>>(lossp);
        loss_kernel<<<BS_, 256>>>(out, targets, lossp);
        fin_loss<<<1, 1>>>(lossp, out + NLOG);
    }
}

// round 16
// speedup vs baseline: 1.4866x; 1.0074x over previous
#include <cuda_runtime.h>
#include <math.h>
#include <stdint.h>

// ---------------- problem constants ----------------
constexpr int B_  = 8;
constexpr int S_  = 512;
constexpr int E_  = 384;
constexpr int H_  = 7;
constexpr int D_  = 54;
constexpr int L_  = 7;
constexpr int V_  = 32000;
constexpr int FF_ = 6 * E_;          // 2304
constexpr int BS_ = B_ * S_;         // 4096
constexpr int HD_ = H_ * D_;         // 378
constexpr int HDP_ = 384;            // padded ocat row width
constexpr int HB_ = 192;             // padded head block: q(64)|k(64)|v(64)
constexpr int QLD_ = H_ * HB_;       // 1344
constexpr float EPS_ = 1e-5f;

typedef long long ll;

// ---------------- scratch ----------------
__device__ float g_x   [BS_ * E_];
__device__ float g_xn  [BS_ * E_];          // tf32-rounded
__device__ float g_qkv [BS_ * QLD_];        // tf32-rounded
__device__ float g_wqkv[L_ * E_ * QLD_];    // tf32-rounded
__device__ float g_bqkv[L_ * QLD_];
__device__ float g_wc  [L_ * HDP_ * E_];    // tf32-rounded, zero-padded
__device__ float g_w1r [L_ * E_ * FF_];     // tf32-rounded W1
__device__ float g_w2r [L_ * FF_ * E_];     // tf32-rounded W2
__device__ float g_woutr[E_ * V_];          // tf32-rounded Wout
__device__ float g_ocat[BS_ * HDP_];        // tf32-rounded, pad cols stay 0
__device__ float g_h   [BS_ * FF_];         // tf32-rounded
__device__ float g_loss;

#define FLAG_ACC    2
#define FLAG_GELU   4
#define FLAG_RND    8

__device__ __forceinline__ float gelu_f(float x) {
    return 0.5f * x * (1.0f + erff(x * 0.70710678118654752f));
}
__device__ __forceinline__ uint32_t f2tf32(float x) {
    uint32_t r;
    asm("cvt.rna.tf32.f32 %0, %1;" : "=r"(r) : "f"(x));
    return r;
}
__device__ __forceinline__ float rnd_tf32(float x) {
    return __uint_as_float(f2tf32(x));
}
__device__ __forceinline__ uint32_t smem_u32(const void* p) {
    uint32_t a;
    asm("{ .reg .u64 t; cvta.to.shared.u64 t, %1; cvt.u32.u64 %0, t; }"
        : "=r"(a) : "l"(p));
    return a;
}
#define MMA_TF32(ACC, A0, A1, A2, A3, B0, B1)                                  \
    asm volatile(                                                              \
        "mma.sync.aligned.m16n8k8.row.col.f32.tf32.tf32.f32 "                  \
        "{%0,%1,%2,%3}, {%4,%5,%6,%7}, {%8,%9}, {%0,%1,%2,%3};"                \
        : "+f"((ACC)[0]), "+f"((ACC)[1]), "+f"((ACC)[2]), "+f"((ACC)[3])       \
        : "r"(A0), "r"(A1), "r"(A2), "r"(A3), "r"(B0), "r"(B1))
#define CP_ASYNC16(DST, SRC)                                                   \
    asm volatile("cp.async.cg.shared.global [%0], [%1], 16;"                   \
                 :: "r"(DST), "l"(SRC))
#define CP_ASYNC16Z(DST, SRC, BYTES)                                           \
    asm volatile("cp.async.cg.shared.global [%0], [%1], 16, %2;"               \
                 :: "r"(DST), "l"(SRC), "r"(BYTES))
#define CP_COMMIT() asm volatile("cp.async.commit_group;")
#define CP_WAIT2()  asm volatile("cp.async.wait_group 2;")

// =====================================================================
// tf32 mma.sync GEMM, 4-stage cp.async pipeline. OPERANDS MUST BE
// PRE-ROUNDED TO TF32 (producer-side). Mainloop is pure LDS -> MMA.
// Requires: M%BM==0, K%16==0, lda%4==0, ldb%4==0.
//   big  : BM=256, warp tile 64x64 (NT=8)
//   small: BM=128, warp tile 64x32 (NT=4)
// =====================================================================
template<int BM, int NT>
__global__ void __launch_bounds__(256, 1)
tc_gemm(const float* __restrict__ A, const float* __restrict__ Bm,
        const float* __restrict__ bias, float* __restrict__ C,
        int M, int N, int K,
        int lda, int ldb, int ldc, int zdiv,
        ll sA1, ll sA2, ll sB1, ll sB2, ll sC1, ll sC2,
        float alpha, int flags)
{
    constexpr int MWARPS = BM / 64;
    constexpr int ASTR = 20;
    constexpr int BSTR = 132;
    constexpr int AW = BM * ASTR;
    constexpr int SWORDS = AW + 16 * BSTR;
    constexpr int AE4 = BM / 64;

    extern __shared__ uint32_t sm[];

    {
        const int z = blockIdx.z;
        const int zq = z / zdiv, zr = z - zq * zdiv;
        A  += (ll)zq * sA1 + (ll)zr * sA2;
        Bm += (ll)zq * sB1 + (ll)zr * sB2;
        C  += (ll)zq * sC1 + (ll)zr * sC2;
    }

    const int row0 = blockIdx.y * BM;
    const int col0 = blockIdx.x * 128;
    const int tid  = threadIdx.x;
    const int warp = tid >> 5;
    const int lane = tid & 31;
    const int wm = (warp % MWARPS) * 64;
    const int wn = (warp / MWARPS) * (NT * 8);
    const int lr = lane >> 2;
    const int lc = lane & 3;

    float acc[4][NT][4];
#pragma unroll
    for (int mt = 0; mt < 4; mt++)
#pragma unroll
        for (int nt = 0; nt < NT; nt++)
#pragma unroll
            for (int c = 0; c < 4; c++) acc[mt][nt][c] = 0.f;

    const int nk = K >> 4;
    const uint32_t smBase = smem_u32(sm);

    auto issue = [&](int kt) {
        const int st = kt & 3;
        const uint32_t aBase = smBase + (uint32_t)st * SWORDS * 4;
        const uint32_t bBase = aBase + AW * 4;
        const int k0 = kt << 4;
#pragma unroll
        for (int i = 0; i < AE4; i++) {
            int e = tid + i * 256;
            int m = e >> 2, kq = e & 3;
            const float* src = A + (ll)(row0 + m) * lda + k0 + kq * 4;
            CP_ASYNC16(aBase + (uint32_t)(m * ASTR + kq * 4) * 4, src);
        }
#pragma unroll
        for (int i = 0; i < 2; i++) {
            int e = tid + i * 256;
            int k = e >> 5, n4 = (e & 31) << 2;
            const bool ok = (col0 + n4 < N);
            const float* src = ok ? (Bm + (ll)(k0 + k) * ldb + col0 + n4) : Bm;
            CP_ASYNC16Z(bBase + (uint32_t)(k * BSTR + n4) * 4, src, ok ? 16 : 0);
        }
    };

    issue(0); CP_COMMIT();
    issue(1); CP_COMMIT();
    issue(2); CP_COMMIT();

    for (int kt = 0; kt < nk; kt++) {
        CP_WAIT2();
        __syncthreads();
        if (kt + 3 < nk) issue(kt + 3);
        CP_COMMIT();

        const uint32_t* As = sm + (kt & 3) * SWORDS;
        const uint32_t* Bs = As + AW;

#pragma unroll
        for (int ks = 0; ks < 2; ks++) {
            const int kk = ks * 8;
            uint32_t af[4][4], bf[NT][2];
#pragma unroll
            for (int mt = 0; mt < 4; mt++) {
                const uint32_t* Ab = As + (wm + mt * 16 + lr) * ASTR + kk + lc;
                af[mt][0] = Ab[0];
                af[mt][1] = Ab[8 * ASTR];
                af[mt][2] = Ab[4];
                af[mt][3] = Ab[8 * ASTR + 4];
            }
#pragma unroll
            for (int nt = 0; nt < NT; nt++) {
                const int n0 = wn + nt * 8 + lr;
                bf[nt][0] = Bs[(kk + lc) * BSTR + n0];
                bf[nt][1] = Bs[(kk + lc + 4) * BSTR + n0];
            }
#pragma unroll
            for (int mt = 0; mt < 4; mt++)
#pragma unroll
                for (int nt = 0; nt < NT; nt++)
                    MMA_TF32(acc[mt][nt], af[mt][0], af[mt][1], af[mt][2], af[mt][3],
                             bf[nt][0], bf[nt][1]);
        }
    }

    // ---- epilogue ----
    const bool doacc = (flags & FLAG_ACC);
    const bool dogel = (flags & FLAG_GELU);
    const bool dornd = (flags & FLAG_RND);
#pragma unroll
    for (int mt = 0; mt < 4; mt++)
#pragma unroll
        for (int nt = 0; nt < NT; nt++) {
            int rb = row0 + wm + mt * 16 + lr;
            int cb = col0 + wn + nt * 8 + lc * 2;
#pragma unroll
            for (int h = 0; h < 2; h++) {
                int r = rb + h * 8;
                int c = cb;
                if (c >= N) continue;
                float v0 = acc[mt][nt][h * 2 + 0] * alpha;
                float v1 = acc[mt][nt][h * 2 + 1] * alpha;
                if (bias) {
                    v0 += bias[c];
                    if (c + 1 < N) v1 += bias[c + 1];
                }
                if (dogel) { v0 = gelu_f(v0); v1 = gelu_f(v1); }
                if (dornd) { v0 = rnd_tf32(v0); v1 = rnd_tf32(v1); }
                float* Cp = C + (ll)r * ldc + c;
                if (c + 1 < N) {
                    if (doacc) {
                        float2 o = *reinterpret_cast<const float2*>(Cp);
                        v0 += o.x; v1 += o.y;
                    }
                    *reinterpret_cast<float2*>(Cp) = make_float2(v0, v1);
                } else {
                    if (doacc) v0 += Cp[0];
                    Cp[0] = v0;
                }
            }
        }
}

// =====================================================================
// Fused causal flash attention. qkv is pre-rounded tf32; k/v copied raw,
// q rounded after scale, P rounded, ocat written rounded.
// =====================================================================
constexpr int QSTR_F = 132, KSTR_F = 132, VSTR_F = 68, PSTR_F = 132;
constexpr int OFF_Q = 0;
constexpr int OFF_K = OFF_Q + 64 * QSTR_F;
constexpr int OFF_V = OFF_K + 64 * KSTR_F;
constexpr int OFF_P = OFF_V + 128 * VSTR_F;
constexpr int OFF_SC = OFF_P + 128 * PSTR_F;
constexpr int OFF_L  = OFF_SC + 128;
constexpr int FLASH_WORDS = OFF_L + 128;

__global__ void __launch_bounds__(256, 1)
flash_kernel(const float* __restrict__ qkv, float* __restrict__ ocat)
{
    extern __shared__ uint32_t fs[];
    float* fsf = reinterpret_cast<float*>(fs);

    const int qt = (int)gridDim.x - 1 - (int)blockIdx.x;
    const int z = blockIdx.y;
    const int b = z / H_, h = z % H_;
    const ll browq = (ll)b * S_ + (ll)qt * 128;
    const int tid = threadIdx.x;
    const int warp = tid >> 5, lane = tid & 31;
    const int lr = lane >> 2, lc = lane & 3;
    const float scale = rsqrtf((float)D_);

    {
        const float* qp = qkv + browq * QLD_ + h * HB_;
#pragma unroll
        for (int i = 0; i < 8; i++) {
            int e = tid + i * 256;
            int m = e >> 4, kq = e & 15;
            float4 v = *reinterpret_cast<const float4*>(qp + (ll)m * QLD_ + kq * 4);
            uint32_t* dst = fs + OFF_Q + m;
            dst[(kq * 4 + 0) * QSTR_F] = f2tf32(v.x * scale);
            dst[(kq * 4 + 1) * QSTR_F] = f2tf32(v.y * scale);
            dst[(kq * 4 + 2) * QSTR_F] = f2tf32(v.z * scale);
            dst[(kq * 4 + 3) * QSTR_F] = f2tf32(v.w * scale);
        }
    }

    float oacc[2][4][4];
#pragma unroll
    for (int mt = 0; mt < 2; mt++)
#pragma unroll
        for (int nt = 0; nt < 4; nt++)
#pragma unroll
            for (int c = 0; c < 4; c++) oacc[mt][nt][c] = 0.f;

    const int owm = (warp & 3) * 32, own = (warp >> 2) * 32;
    const int swm = warp * 16;
    float mrow0 = -1e30f, mrow1 = -1e30f;
    float lrow0 = 0.f, lrow1 = 0.f;

    for (int kt = 0; kt <= qt; kt++) {
        const ll browk = (ll)b * S_ + (ll)kt * 128;
        {
            const float* kp = qkv + browk * QLD_ + h * HB_ + 64;
#pragma unroll
            for (int i = 0; i < 8; i++) {
                int e = tid + i * 256;
                int n = e >> 4, kq = e & 15;
                uint4 v = *reinterpret_cast<const uint4*>(kp + (ll)n * QLD_ + kq * 4);
                uint32_t* dst = fs + OFF_K + n;
                dst[(kq * 4 + 0) * KSTR_F] = v.x;
                dst[(kq * 4 + 1) * KSTR_F] = v.y;
                dst[(kq * 4 + 2) * KSTR_F] = v.z;
                dst[(kq * 4 + 3) * KSTR_F] = v.w;
            }
            const float* vp = qkv + browk * QLD_ + h * HB_ + 128;
#pragma unroll
            for (int i = 0; i < 8; i++) {
                int e = tid + i * 256;
                int kk2 = e >> 4, dq = e & 15;
                uint4 v = *reinterpret_cast<const uint4*>(vp + (ll)kk2 * QLD_ + dq * 4);
                *reinterpret_cast<uint4*>(fs + OFF_V + kk2 * VSTR_F + dq * 4) = v;
            }
        }
        __syncthreads();

        float s[16][4];
#pragma unroll
        for (int nt = 0; nt < 16; nt++)
#pragma unroll
            for (int c = 0; c < 4; c++) s[nt][c] = 0.f;

#pragma unroll
        for (int ks = 0; ks < 8; ks++) {
            const int kk = ks * 8;
            uint32_t a0 = fs[OFF_Q + (kk + lc) * QSTR_F + swm + lr];
            uint32_t a1 = fs[OFF_Q + (kk + lc) * QSTR_F + swm + lr + 8];
            uint32_t a2 = fs[OFF_Q + (kk + lc + 4) * QSTR_F + swm + lr];
            uint32_t a3 = fs[OFF_Q + (kk + lc + 4) * QSTR_F + swm + lr + 8];
#pragma unroll
            for (int nt = 0; nt < 16; nt++) {
                uint32_t b0 = fs[OFF_K + (kk + lc) * KSTR_F + nt * 8 + lr];
                uint32_t b1 = fs[OFF_K + (kk + lc + 4) * KSTR_F + nt * 8 + lr];
                MMA_TF32(s[nt], a0, a1, a2, a3, b0, b1);
            }
        }

        if (kt == qt) {
#pragma unroll
            for (int nt = 0; nt < 16; nt++) {
                int c0 = nt * 8 + 2 * lc;
                int r0 = swm + lr, r1 = r0 + 8;
                if (c0 > r0)     s[nt][0] = -1e30f;
                if (c0 + 1 > r0) s[nt][1] = -1e30f;
                if (c0 > r1)     s[nt][2] = -1e30f;
                if (c0 + 1 > r1) s[nt][3] = -1e30f;
            }
        }

        float mx0 = -1e30f, mx1 = -1e30f;
#pragma unroll
        for (int nt = 0; nt < 16; nt++) {
            mx0 = fmaxf(mx0, fmaxf(s[nt][0], s[nt][1]));
            mx1 = fmaxf(mx1, fmaxf(s[nt][2], s[nt][3]));
        }
        mx0 = fmaxf(mx0, __shfl_xor_sync(0xffffffffu, mx0, 1));
        mx0 = fmaxf(mx0, __shfl_xor_sync(0xffffffffu, mx0, 2));
        mx1 = fmaxf(mx1, __shfl_xor_sync(0xffffffffu, mx1, 1));
        mx1 = fmaxf(mx1, __shfl_xor_sync(0xffffffffu, mx1, 2));
        float mn0 = fmaxf(mrow0, mx0), mn1 = fmaxf(mrow1, mx1);
        float sc0 = __expf(mrow0 - mn0), sc1 = __expf(mrow1 - mn1);

        float sum0 = 0.f, sum1 = 0.f;
#pragma unroll
        for (int nt = 0; nt < 16; nt++) {
            float p00 = __expf(s[nt][0] - mn0);
            float p01 = __expf(s[nt][1] - mn0);
            float p10 = __expf(s[nt][2] - mn1);
            float p11 = __expf(s[nt][3] - mn1);
            sum0 += p00 + p01;
            sum1 += p10 + p11;
            const int key = nt * 8 + 2 * lc;
            fs[OFF_P + (key + 0) * PSTR_F + swm + lr]     = f2tf32(p00);
            fs[OFF_P + (key + 1) * PSTR_F + swm + lr]     = f2tf32(p01);
            fs[OFF_P + (key + 0) * PSTR_F + swm + lr + 8] = f2tf32(p10);
            fs[OFF_P + (key + 1) * PSTR_F + swm + lr + 8] = f2tf32(p11);
        }
        sum0 += __shfl_xor_sync(0xffffffffu, sum0, 1);
        sum0 += __shfl_xor_sync(0xffffffffu, sum0, 2);
        sum1 += __shfl_xor_sync(0xffffffffu, sum1, 1);
        sum1 += __shfl_xor_sync(0xffffffffu, sum1, 2);
        lrow0 = lrow0 * sc0 + sum0;
        lrow1 = lrow1 * sc1 + sum1;
        mrow0 = mn0; mrow1 = mn1;
        if (lc == 0) {
            fsf[OFF_SC + swm + lr]     = sc0;
            fsf[OFF_SC + swm + lr + 8] = sc1;
        }
        __syncthreads();

        float rs[2][2];
        rs[0][0] = fsf[OFF_SC + owm + lr];
        rs[0][1] = fsf[OFF_SC + owm + lr + 8];
        rs[1][0] = fsf[OFF_SC + owm + 16 + lr];
        rs[1][1] = fsf[OFF_SC + owm + 16 + lr + 8];
#pragma unroll
        for (int mt = 0; mt < 2; mt++)
#pragma unroll
            for (int nt = 0; nt < 4; nt++) {
                oacc[mt][nt][0] *= rs[mt][0];
                oacc[mt][nt][1] *= rs[mt][0];
                oacc[mt][nt][2] *= rs[mt][1];
                oacc[mt][nt][3] *= rs[mt][1];
            }
#pragma unroll
        for (int ks = 0; ks < 16; ks++) {
            const int kk = ks * 8;
            uint32_t a[2][4];
#pragma unroll
            for (int mt = 0; mt < 2; mt++) {
                int m0 = owm + mt * 16 + lr;
                a[mt][0] = fs[OFF_P + (kk + lc) * PSTR_F + m0];
                a[mt][1] = fs[OFF_P + (kk + lc) * PSTR_F + m0 + 8];
                a[mt][2] = fs[OFF_P + (kk + lc + 4) * PSTR_F + m0];
                a[mt][3] = fs[OFF_P + (kk + lc + 4) * PSTR_F + m0 + 8];
            }
#pragma unroll
            for (int nt = 0; nt < 4; nt++) {
                uint32_t b0 = fs[OFF_V + (kk + lc) * VSTR_F + own + nt * 8 + lr];
                uint32_t b1 = fs[OFF_V + (kk + lc + 4) * VSTR_F + own + nt * 8 + lr];
#pragma unroll
                for (int mt = 0; mt < 2; mt++)
                    MMA_TF32(oacc[mt][nt], a[mt][0], a[mt][1], a[mt][2], a[mt][3], b0, b1);
            }
        }
        __syncthreads();
    }

    if (lc == 0) {
        fsf[OFF_L + swm + lr]     = 1.f / lrow0;
        fsf[OFF_L + swm + lr + 8] = 1.f / lrow1;
    }
    __syncthreads();
    float il[2][2];
    il[0][0] = fsf[OFF_L + owm + lr];
    il[0][1] = fsf[OFF_L + owm + lr + 8];
    il[1][0] = fsf[OFF_L + owm + 16 + lr];
    il[1][1] = fsf[OFF_L + owm + 16 + lr + 8];

#pragma unroll
    for (int mt = 0; mt < 2; mt++)
#pragma unroll
        for (int nt = 0; nt < 4; nt++) {
            int d = own + nt * 8 + 2 * lc;
#pragma unroll
            for (int hf = 0; hf < 2; hf++) {
                int r = owm + mt * 16 + lr + hf * 8;
                float v0 = rnd_tf32(oacc[mt][nt][hf * 2 + 0] * il[mt][hf]);
                float v1 = rnd_tf32(oacc[mt][nt][hf * 2 + 1] * il[mt][hf]);
                float* orow = ocat + (browq + r) * HDP_ + h * D_;
                if (d < D_)     orow[d] = v0;
                if (d + 1 < D_) orow[d + 1] = v1;
            }
        }
}

// ---------------- weight repacks (all outputs tf32-rounded) ----------------
__global__ void repack_qkv(const float* __restrict__ Wq, const float* __restrict__ Wk,
                           const float* __restrict__ Wv, float* __restrict__ Wp)
{
    ll idx = (ll)blockIdx.x * 256 + threadIdx.x;
    const ll total = (ll)L_ * E_ * QLD_;
    if (idx >= total) return;
    int c = (int)(idx % QLD_);
    ll le = idx / QLD_;
    int e = (int)(le % E_);
    int l = (int)(le / E_);
    int h = c / HB_, r = c % HB_, s = r >> 6, d = r & 63;
    float v = 0.f;
    if (d < D_) {
        const float* W = (s == 0) ? Wq : (s == 1) ? Wk : Wv;
        v = rnd_tf32(W[(((ll)l * H_ + h) * E_ + e) * D_ + d]);
    }
    Wp[idx] = v;
}
__global__ void repack_bias(const float* __restrict__ bq, const float* __restrict__ bk,
                            const float* __restrict__ bv, float* __restrict__ bp)
{
    int idx = blockIdx.x * 256 + threadIdx.x;
    if (idx >= L_ * QLD_) return;
    int c = idx % QLD_, l = idx / QLD_;
    int h = c / HB_, r = c % HB_, s = r >> 6, d = r & 63;
    float v = 0.f;
    if (d < D_) {
        const float* bb = (s == 0) ? bq : (s == 1) ? bk : bv;
        v = bb[((ll)l * H_ + h) * D_ + d];
    }
    bp[idx] = v;
}
__global__ void repack_wc(const float* __restrict__ Wc, float* __restrict__ Wp)
{
    ll idx = (ll)blockIdx.x * 256 + threadIdx.x;
    const ll total = (ll)L_ * HDP_ * E_;
    if (idx >= total) return;
    int e = (int)(idx % E_);
    ll lr = idx / E_;
    int r = (int)(lr % HDP_);
    int l = (int)(lr / HDP_);
    Wp[idx] = (r < HD_) ? rnd_tf32(Wc[((ll)l * HD_ + r) * E_ + e]) : 0.f;
}
// elementwise tf32 rounding copy (n % 4 == 0)
__global__ void round_copy(const float* __restrict__ src, float* __restrict__ dst, ll n4)
{
    ll i = ((ll)blockIdx.x * 256 + threadIdx.x);
    if (i >= n4) return;
    float4 v = *reinterpret_cast<const float4*>(src + i * 4);
    v.x = rnd_tf32(v.x); v.y = rnd_tf32(v.y);
    v.z = rnd_tf32(v.z); v.w = rnd_tf32(v.w);
    *reinterpret_cast<float4*>(dst + i * 4) = v;
}

// ---------------- pointwise / reductions ----------------
__global__ void embed_kernel(const int* __restrict__ ids,
                             const float* __restrict__ tok,
                             const float* __restrict__ pos,
                             float* __restrict__ x)
{
    int row = blockIdx.x;
    int s = row % S_;
    ll id = ids[row];
    float* xr = x + (ll)row * E_;
    const float* tr = tok + id * E_;
    const float* pr = pos + (ll)s * E_;
    for (int i = threadIdx.x; i < E_; i += blockDim.x)
        xr[i] = tr[i] + pr[i];
}

// LayerNorm; output tf32-rounded (consumed only as GEMM A operand)
__global__ void ln_kernel(const float* __restrict__ x,
                          const float* __restrict__ g,
                          const float* __restrict__ b,
                          float* __restrict__ y)
{
    int row = blockIdx.x;
    const float* xr = x + (ll)row * E_;
    float s = 0.f, ss = 0.f;
    for (int i = threadIdx.x; i < E_; i += 128) {
        float v = xr[i];
        s += v; ss += v * v;
    }
#pragma unroll
    for (int o = 16; o > 0; o >>= 1) {
        s  += __shfl_xor_sync(0xffffffffu, s, o);
        ss += __shfl_xor_sync(0xffffffffu, ss, o);
    }
    __shared__ float sh_s[4], sh_ss[4];
    int w = threadIdx.x >> 5;
    if ((threadIdx.x & 31) == 0) { sh_s[w] = s; sh_ss[w] = ss; }
    __syncthreads();
    s  = sh_s[0] + sh_s[1] + sh_s[2] + sh_s[3];
    ss = sh_ss[0] + sh_ss[1] + sh_ss[2] + sh_ss[3];
    float mean = s / E_;
    float var  = ss / E_ - mean * mean;
    float rstd = rsqrtf(var + EPS_);
    float* yr = y + (ll)row * E_;
    for (int i = threadIdx.x; i < E_; i += 128)
        yr[i] = rnd_tf32((xr[i] - mean) * rstd * g[i] + b[i]);
}

__global__ void loss_kernel(const float* __restrict__ logits,
                            const int* __restrict__ tgt,
                            float* __restrict__ acc)
{
    int row = blockIdx.x;
    const float* p = logits + (ll)row * V_;
    __shared__ float sh[8];
    float mx = -1e30f;
    for (int j = threadIdx.x; j < V_; j += 256) mx = fmaxf(mx, p[j]);
#pragma unroll
    for (int o = 16; o > 0; o >>= 1) mx = fmaxf(mx, __shfl_xor_sync(0xffffffffu, mx, o));
    int w = threadIdx.x >> 5;
    if ((threadIdx.x & 31) == 0) sh[w] = mx;
    __syncthreads();
    mx = sh[0];
#pragma unroll
    for (int i = 1; i < 8; i++) mx = fmaxf(mx, sh[i]);
    __syncthreads();
    float sum = 0.f;
    for (int j = threadIdx.x; j < V_; j += 256) sum += expf(p[j] - mx);
#pragma unroll
    for (int o = 16; o > 0; o >>= 1) sum += __shfl_xor_sync(0xffffffffu, sum, o);
    if ((threadIdx.x & 31) == 0) sh[w] = sum;
    __syncthreads();
    if (threadIdx.x == 0) {
        float tot = 0.f;
#pragma unroll
        for (int i = 0; i < 8; i++) tot += sh[i];
        float lse = mx + logf(tot);
        atomicAdd(acc, p[tgt[row]] - lse);
    }
}

__global__ void zero_loss(float* a) { *a = 0.f; }
__global__ void fin_loss(const float* a, float* out) { *out = -(*a) / (float)BS_; }

// ---------------- host driver ----------------
constexpr int SMEM_BIG   = 4 * (256 * 20 + 16 * 132) * 4;
constexpr int SMEM_SMALL = 4 * (128 * 20 + 16 * 132) * 4;
constexpr int SMEM_FLASH = FLASH_WORDS * 4;

static void gemm(bool big, const float* A, const float* Bm, const float* bias, float* C,
                 int M, int N, int K, int lda, int ldb, int ldc,
                 int batch, int zdiv,
                 ll sA1, ll sA2, ll sB1, ll sB2, ll sC1, ll sC2,
                 float alpha, int flags)
{
    if (big) {
        dim3 grid((N + 127) / 128, M / 256, batch);
        tc_gemm<256, 8><<<grid, 256, SMEM_BIG>>>(
            A, Bm, bias, C, M, N, K, lda, ldb, ldc,
            zdiv, sA1, sA2, sB1, sB2, sC1, sC2, alpha, flags);
    } else {
        dim3 grid((N + 127) / 128, M / 128, batch);
        tc_gemm<128, 4><<<grid, 256, SMEM_SMALL>>>(
            A, Bm, bias, C, M, N, K, lda, ldb, ldc,
            zdiv, sA1, sA2, sB1, sB2, sC1, sC2, alpha, flags);
    }
}

extern "C" void kernel_launch(void* const* d_in, const int* in_sizes, int n_in,
                              void* d_out, int out_size)
{
    const int*   input_ids = (const int*)d_in[0];
    const int*   targets   = (const int*)d_in[1];
    const float* tok_emb   = (const float*)d_in[2];
    const float* pos_emb   = (const float*)d_in[3];
    const float* Wq  = (const float*)d_in[4];
    const float* bq  = (const float*)d_in[5];
    const float* Wk  = (const float*)d_in[6];
    const float* bk  = (const float*)d_in[7];
    const float* Wv  = (const float*)d_in[8];
    const float* bv  = (const float*)d_in[9];
    const float* Wc  = (const float*)d_in[10];
    const float* bc  = (const float*)d_in[11];
    const float* g1  = (const float*)d_in[12];
    const float* b1  = (const float*)d_in[13];
    const float* g2  = (const float*)d_in[14];
    const float* b2  = (const float*)d_in[15];
    const float* W1  = (const float*)d_in[16];
    const float* bf1 = (const float*)d_in[17];
    const float* W2  = (const float*)d_in[18];
    const float* bf2 = (const float*)d_in[19];
    const float* gf   = (const float*)d_in[20];
    const float* bfin = (const float*)d_in[21];
    const float* Wout = (const float*)d_in[22];
    const float* bout = (const float*)d_in[23];
    float* out = (float*)d_out;

    cudaFuncSetAttribute(tc_gemm<256, 8>,
                         cudaFuncAttributeMaxDynamicSharedMemorySize, SMEM_BIG);
    cudaFuncSetAttribute(tc_gemm<128, 4>,
                         cudaFuncAttributeMaxDynamicSharedMemorySize, SMEM_SMALL);
    cudaFuncSetAttribute(flash_kernel,
                         cudaFuncAttributeMaxDynamicSharedMemorySize, SMEM_FLASH);

    float *x, *xn, *qkv, *wqkv, *bqkv, *wcp, *w1r, *w2r, *woutr, *ocat, *hbuf, *lossp;
    cudaGetSymbolAddress((void**)&x,    g_x);
    cudaGetSymbolAddress((void**)&xn,   g_xn);
    cudaGetSymbolAddress((void**)&qkv,  g_qkv);
    cudaGetSymbolAddress((void**)&wqkv, g_wqkv);
    cudaGetSymbolAddress((void**)&bqkv, g_bqkv);
    cudaGetSymbolAddress((void**)&wcp,  g_wc);
    cudaGetSymbolAddress((void**)&w1r,  g_w1r);
    cudaGetSymbolAddress((void**)&w2r,  g_w2r);
    cudaGetSymbolAddress((void**)&woutr, g_woutr);
    cudaGetSymbolAddress((void**)&ocat, g_ocat);
    cudaGetSymbolAddress((void**)&hbuf, g_h);
    cudaGetSymbolAddress((void**)&lossp, g_loss);

    {
        ll total = (ll)L_ * E_ * QLD_;
        repack_qkv<<<(int)((total + 255) / 256), 256>>>(Wq, Wk, Wv, wqkv);
        repack_bias<<<(L_ * QLD_ + 255) / 256, 256>>>(bq, bk, bv, bqkv);
        ll tot2 = (ll)L_ * HDP_ * E_;
        repack_wc<<<(int)((tot2 + 255) / 256), 256>>>(Wc, wcp);
        ll n1 = (ll)L_ * E_ * FF_ / 4;
        round_copy<<<(int)((n1 + 255) / 256), 256>>>(W1, w1r, n1);
        round_copy<<<(int)((n1 + 255) / 256), 256>>>(W2, w2r, n1);
        ll n2 = (ll)E_ * V_ / 4;
        round_copy<<<(int)((n2 + 255) / 256), 256>>>(Wout, woutr, n2);
    }

    embed_kernel<<<BS_, 128>>>(input_ids, tok_emb, pos_emb, x);

    for (int l = 0; l < L_; l++) {
        ln_kernel<<<BS_, 128>>>(x, g1 + l * E_, b1 + l * E_, xn);

        // fused QKV: [4096,384] @ [384,1344], output rounded for flash
        gemm(true, xn, wqkv + (ll)l * E_ * QLD_, bqkv + (ll)l * QLD_, qkv,
             BS_, QLD_, E_, E_, QLD_, QLD_,
             1, 1, 0, 0, 0, 0, 0, 0, 1.f, FLAG_RND);

        // fused causal attention -> ocat (rounded, stride 384)
        {
            dim3 grid(S_ / 128, B_ * H_);
            flash_kernel<<<grid, 256, SMEM_FLASH>>>(qkv, ocat);
        }

        // x += ocat @ Wc_pad + bc  (residual: NOT rounded)
        gemm(false, ocat, wcp + (ll)l * HDP_ * E_, bc + l * E_, x,
             BS_, E_, HDP_, HDP_, E_, E_,
             1, 1, 0, 0, 0, 0, 0, 0, 1.f, FLAG_ACC);

        ln_kernel<<<BS_, 128>>>(x, g2 + l * E_, b2 + l * E_, xn);

        // h = gelu(xn @ W1 + bf1), rounded for FF2
        gemm(true, xn, w1r + (ll)l * E_ * FF_, bf1 + (ll)l * FF_, hbuf,
             BS_, FF_, E_, E_, FF_, FF_,
             1, 1, 0, 0, 0, 0, 0, 0, 1.f, FLAG_GELU | FLAG_RND);

        // x += h @ W2 + bf2  (residual: NOT rounded)
        gemm(false, hbuf, w2r + (ll)l * FF_ * E_, bf2 + l * E_, x,
             BS_, E_, FF_, FF_, E_, E_,
             1, 1, 0, 0, 0, 0, 0, 0, 1.f, FLAG_ACC);
    }

    ln_kernel<<<BS_, 128>>>(x, gf, bfin, xn);
    gemm(true, xn, woutr, bout, out,
         BS_, V_, E_, E_, V_, V_,
         1, 1, 0, 0, 0, 0, 0, 0, 1.f, 0);

    const ll NLOG = (ll)BS_ * V_;
    if ((ll)out_size > NLOG) {
        zero_loss<<<1, 1>>>(lossp);
        loss_kernel<<<BS_, 256>>>(out, targets, lossp);
        fin_loss<<<1, 1>>>(lossp, out + NLOG);
    }
}

// round 17
// speedup vs baseline: 1.7268x; 1.1615x over previous
#include <cuda_runtime.h>
#include <math.h>
#include <stdint.h>

// ---------------- problem constants ----------------
constexpr int B_  = 8;
constexpr int S_  = 512;
constexpr int E_  = 384;
constexpr int H_  = 7;
constexpr int D_  = 54;
constexpr int L_  = 7;
constexpr int V_  = 32000;
constexpr int FF_ = 6 * E_;          // 2304
constexpr int BS_ = B_ * S_;         // 4096
constexpr int HD_ = H_ * D_;         // 378
constexpr int HDP_ = 384;            // padded ocat row width
constexpr int HB_ = 192;             // padded head block: q(64)|k(64)|v(64)
constexpr int QLD_ = H_ * HB_;       // 1344
constexpr float EPS_ = 1e-5f;

typedef long long ll;

// ---------------- scratch ----------------
__device__ float g_x   [BS_ * E_];
__device__ float g_xn  [BS_ * E_];          // tf32-rounded
__device__ float g_qkv [BS_ * QLD_];        // tf32-rounded
__device__ float g_wqkv[L_ * E_ * QLD_];    // tf32-rounded
__device__ float g_bqkv[L_ * QLD_];
__device__ float g_wc  [L_ * HDP_ * E_];    // tf32-rounded, zero-padded
__device__ float g_w1r [L_ * E_ * FF_];     // tf32-rounded W1
__device__ float g_w2r [L_ * FF_ * E_];     // tf32-rounded W2
__device__ float g_woutr[E_ * V_];          // tf32-rounded Wout
__device__ float g_ocat[BS_ * HDP_];        // tf32-rounded, pad cols stay 0
__device__ float g_h   [BS_ * FF_];         // tf32-rounded
__device__ float g_loss;

#define FLAG_ACC    2
#define FLAG_GELU   4
#define FLAG_RND    8

__device__ __forceinline__ float gelu_f(float x) {
    return 0.5f * x * (1.0f + erff(x * 0.70710678118654752f));
}
__device__ __forceinline__ uint32_t f2tf32(float x) {
    uint32_t r;
    asm("cvt.rna.tf32.f32 %0, %1;" : "=r"(r) : "f"(x));
    return r;
}
__device__ __forceinline__ float rnd_tf32(float x) {
    return __uint_as_float(f2tf32(x));
}
__device__ __forceinline__ uint32_t smem_u32(const void* p) {
    uint32_t a;
    asm("{ .reg .u64 t; cvta.to.shared.u64 t, %1; cvt.u32.u64 %0, t; }"
        : "=r"(a) : "l"(p));
    return a;
}
#define MMA_TF32(ACC, A0, A1, A2, A3, B0, B1)                                  \
    asm volatile(                                                              \
        "mma.sync.aligned.m16n8k8.row.col.f32.tf32.tf32.f32 "                  \
        "{%0,%1,%2,%3}, {%4,%5,%6,%7}, {%8,%9}, {%0,%1,%2,%3};"                \
        : "+f"((ACC)[0]), "+f"((ACC)[1]), "+f"((ACC)[2]), "+f"((ACC)[3])       \
        : "r"(A0), "r"(A1), "r"(A2), "r"(A3), "r"(B0), "r"(B1))
#define CP_ASYNC16(DST, SRC)                                                   \
    asm volatile("cp.async.cg.shared.global [%0], [%1], 16;"                   \
                 :: "r"(DST), "l"(SRC))
#define CP_ASYNC16Z(DST, SRC, BYTES)                                           \
    asm volatile("cp.async.cg.shared.global [%0], [%1], 16, %2;"               \
                 :: "r"(DST), "l"(SRC), "r"(BYTES))
#define CP_COMMIT() asm volatile("cp.async.commit_group;")
#define CP_WAIT1()  asm volatile("cp.async.wait_group 1;")

// =====================================================================
// tf32 mma.sync GEMM: BM=128, BN=128, warp tile 64x32, 3-stage cp.async,
// 2 CTAs/SM. Operands pre-rounded to tf32. Mainloop pure LDS -> MMA.
// Requires: M%128==0, K%16==0, lda%4==0, ldb%4==0.
// =====================================================================
constexpr int G_ASTR = 20;
constexpr int G_BSTR = 132;
constexpr int G_AW = 128 * G_ASTR;                 // 2560 words
constexpr int G_SWORDS = G_AW + 16 * G_BSTR;       // 4672 words
constexpr int SMEM_GEMM = 3 * G_SWORDS * 4;        // 56064 B

__global__ void __launch_bounds__(256, 2)
tc_gemm(const float* __restrict__ A, const float* __restrict__ Bm,
        const float* __restrict__ bias, float* __restrict__ C,
        int M, int N, int K,
        int lda, int ldb, int ldc, int zdiv,
        ll sA1, ll sA2, ll sB1, ll sB2, ll sC1, ll sC2,
        float alpha, int flags)
{
    constexpr int NT = 4;
    constexpr int ASTR = G_ASTR;
    constexpr int BSTR = G_BSTR;
    constexpr int AW = G_AW;
    constexpr int SWORDS = G_SWORDS;

    extern __shared__ uint32_t sm[];

    {
        const int z = blockIdx.z;
        const int zq = z / zdiv, zr = z - zq * zdiv;
        A  += (ll)zq * sA1 + (ll)zr * sA2;
        Bm += (ll)zq * sB1 + (ll)zr * sB2;
        C  += (ll)zq * sC1 + (ll)zr * sC2;
    }

    const int row0 = blockIdx.y * 128;
    const int col0 = blockIdx.x * 128;
    const int tid  = threadIdx.x;
    const int warp = tid >> 5;
    const int lane = tid & 31;
    const int wm = (warp & 1) * 64;            // 2 warps in M
    const int wn = (warp >> 1) * 32;           // 4 warps in N
    const int lr = lane >> 2;
    const int lc = lane & 3;

    float acc[4][NT][4];
#pragma unroll
    for (int mt = 0; mt < 4; mt++)
#pragma unroll
        for (int nt = 0; nt < NT; nt++)
#pragma unroll
            for (int c = 0; c < 4; c++) acc[mt][nt][c] = 0.f;

    const int nk = K >> 4;
    const uint32_t smBase = smem_u32(sm);

    auto issue = [&](int kt) {
        const int st = kt % 3;
        const uint32_t aBase = smBase + (uint32_t)st * SWORDS * 4;
        const uint32_t bBase = aBase + AW * 4;
        const int k0 = kt << 4;
        // A: 128 rows x 16k = 512 float4, 2 per thread
#pragma unroll
        for (int i = 0; i < 2; i++) {
            int e = tid + i * 256;
            int m = e >> 2, kq = e & 3;
            const float* src = A + (ll)(row0 + m) * lda + k0 + kq * 4;
            CP_ASYNC16(aBase + (uint32_t)(m * ASTR + kq * 4) * 4, src);
        }
        // B: 16k x 128 = 512 float4, 2 per thread
#pragma unroll
        for (int i = 0; i < 2; i++) {
            int e = tid + i * 256;
            int k = e >> 5, n4 = (e & 31) << 2;
            const bool ok = (col0 + n4 < N);
            const float* src = ok ? (Bm + (ll)(k0 + k) * ldb + col0 + n4) : Bm;
            CP_ASYNC16Z(bBase + (uint32_t)(k * BSTR + n4) * 4, src, ok ? 16 : 0);
        }
    };

    issue(0); CP_COMMIT();
    issue(1); CP_COMMIT();

    for (int kt = 0; kt < nk; kt++) {
        CP_WAIT1();
        __syncthreads();
        if (kt + 2 < nk) issue(kt + 2);
        CP_COMMIT();

        const uint32_t* As = sm + (kt % 3) * SWORDS;
        const uint32_t* Bs = As + AW;

#pragma unroll
        for (int ks = 0; ks < 2; ks++) {
            const int kk = ks * 8;
            uint32_t af[4][4], bf[NT][2];
#pragma unroll
            for (int mt = 0; mt < 4; mt++) {
                const uint32_t* Ab = As + (wm + mt * 16 + lr) * ASTR + kk + lc;
                af[mt][0] = Ab[0];
                af[mt][1] = Ab[8 * ASTR];
                af[mt][2] = Ab[4];
                af[mt][3] = Ab[8 * ASTR + 4];
            }
#pragma unroll
            for (int nt = 0; nt < NT; nt++) {
                const int n0 = wn + nt * 8 + lr;
                bf[nt][0] = Bs[(kk + lc) * BSTR + n0];
                bf[nt][1] = Bs[(kk + lc + 4) * BSTR + n0];
            }
#pragma unroll
            for (int mt = 0; mt < 4; mt++)
#pragma unroll
                for (int nt = 0; nt < NT; nt++)
                    MMA_TF32(acc[mt][nt], af[mt][0], af[mt][1], af[mt][2], af[mt][3],
                             bf[nt][0], bf[nt][1]);
        }
        __syncthreads();
    }

    // ---- epilogue ----
    const bool doacc = (flags & FLAG_ACC);
    const bool dogel = (flags & FLAG_GELU);
    const bool dornd = (flags & FLAG_RND);
#pragma unroll
    for (int mt = 0; mt < 4; mt++)
#pragma unroll
        for (int nt = 0; nt < NT; nt++) {
            int rb = row0 + wm + mt * 16 + lr;
            int cb = col0 + wn + nt * 8 + lc * 2;
#pragma unroll
            for (int h = 0; h < 2; h++) {
                int r = rb + h * 8;
                int c = cb;
                if (c >= N) continue;
                float v0 = acc[mt][nt][h * 2 + 0] * alpha;
                float v1 = acc[mt][nt][h * 2 + 1] * alpha;
                if (bias) {
                    v0 += bias[c];
                    if (c + 1 < N) v1 += bias[c + 1];
                }
                if (dogel) { v0 = gelu_f(v0); v1 = gelu_f(v1); }
                if (dornd) { v0 = rnd_tf32(v0); v1 = rnd_tf32(v1); }
                float* Cp = C + (ll)r * ldc + c;
                if (c + 1 < N) {
                    if (doacc) {
                        float2 o = *reinterpret_cast<const float2*>(Cp);
                        v0 += o.x; v1 += o.y;
                    }
                    *reinterpret_cast<float2*>(Cp) = make_float2(v0, v1);
                } else {
                    if (doacc) v0 += Cp[0];
                    Cp[0] = v0;
                }
            }
        }
}

// =====================================================================
// Fused causal flash attention (unchanged from R16)
// =====================================================================
constexpr int QSTR_F = 132, KSTR_F = 132, VSTR_F = 68, PSTR_F = 132;
constexpr int OFF_Q = 0;
constexpr int OFF_K = OFF_Q + 64 * QSTR_F;
constexpr int OFF_V = OFF_K + 64 * KSTR_F;
constexpr int OFF_P = OFF_V + 128 * VSTR_F;
constexpr int OFF_SC = OFF_P + 128 * PSTR_F;
constexpr int OFF_L  = OFF_SC + 128;
constexpr int FLASH_WORDS = OFF_L + 128;

__global__ void __launch_bounds__(256, 1)
flash_kernel(const float* __restrict__ qkv, float* __restrict__ ocat)
{
    extern __shared__ uint32_t fs[];
    float* fsf = reinterpret_cast<float*>(fs);

    const int qt = (int)gridDim.x - 1 - (int)blockIdx.x;
    const int z = blockIdx.y;
    const int b = z / H_, h = z % H_;
    const ll browq = (ll)b * S_ + (ll)qt * 128;
    const int tid = threadIdx.x;
    const int warp = tid >> 5, lane = tid & 31;
    const int lr = lane >> 2, lc = lane & 3;
    const float scale = rsqrtf((float)D_);

    {
        const float* qp = qkv + browq * QLD_ + h * HB_;
#pragma unroll
        for (int i = 0; i < 8; i++) {
            int e = tid + i * 256;
            int m = e >> 4, kq = e & 15;
            float4 v = *reinterpret_cast<const float4*>(qp + (ll)m * QLD_ + kq * 4);
            uint32_t* dst = fs + OFF_Q + m;
            dst[(kq * 4 + 0) * QSTR_F] = f2tf32(v.x * scale);
            dst[(kq * 4 + 1) * QSTR_F] = f2tf32(v.y * scale);
            dst[(kq * 4 + 2) * QSTR_F] = f2tf32(v.z * scale);
            dst[(kq * 4 + 3) * QSTR_F] = f2tf32(v.w * scale);
        }
    }

    float oacc[2][4][4];
#pragma unroll
    for (int mt = 0; mt < 2; mt++)
#pragma unroll
        for (int nt = 0; nt < 4; nt++)
#pragma unroll
            for (int c = 0; c < 4; c++) oacc[mt][nt][c] = 0.f;

    const int owm = (warp & 3) * 32, own = (warp >> 2) * 32;
    const int swm = warp * 16;
    float mrow0 = -1e30f, mrow1 = -1e30f;
    float lrow0 = 0.f, lrow1 = 0.f;

    for (int kt = 0; kt <= qt; kt++) {
        const ll browk = (ll)b * S_ + (ll)kt * 128;
        {
            const float* kp = qkv + browk * QLD_ + h * HB_ + 64;
#pragma unroll
            for (int i = 0; i < 8; i++) {
                int e = tid + i * 256;
                int n = e >> 4, kq = e & 15;
                uint4 v = *reinterpret_cast<const uint4*>(kp + (ll)n * QLD_ + kq * 4);
                uint32_t* dst = fs + OFF_K + n;
                dst[(kq * 4 + 0) * KSTR_F] = v.x;
                dst[(kq * 4 + 1) * KSTR_F] = v.y;
                dst[(kq * 4 + 2) * KSTR_F] = v.z;
                dst[(kq * 4 + 3) * KSTR_F] = v.w;
            }
            const float* vp = qkv + browk * QLD_ + h * HB_ + 128;
#pragma unroll
            for (int i = 0; i < 8; i++) {
                int e = tid + i * 256;
                int kk2 = e >> 4, dq = e & 15;
                uint4 v = *reinterpret_cast<const uint4*>(vp + (ll)kk2 * QLD_ + dq * 4);
                *reinterpret_cast<uint4*>(fs + OFF_V + kk2 * VSTR_F + dq * 4) = v;
            }
        }
        __syncthreads();

        float s[16][4];
#pragma unroll
        for (int nt = 0; nt < 16; nt++)
#pragma unroll
            for (int c = 0; c < 4; c++) s[nt][c] = 0.f;

#pragma unroll
        for (int ks = 0; ks < 8; ks++) {
            const int kk = ks * 8;
            uint32_t a0 = fs[OFF_Q + (kk + lc) * QSTR_F + swm + lr];
            uint32_t a1 = fs[OFF_Q + (kk + lc) * QSTR_F + swm + lr + 8];
            uint32_t a2 = fs[OFF_Q + (kk + lc + 4) * QSTR_F + swm + lr];
            uint32_t a3 = fs[OFF_Q + (kk + lc + 4) * QSTR_F + swm + lr + 8];
#pragma unroll
            for (int nt = 0; nt < 16; nt++) {
                uint32_t b0 = fs[OFF_K + (kk + lc) * KSTR_F + nt * 8 + lr];
                uint32_t b1 = fs[OFF_K + (kk + lc + 4) * KSTR_F + nt * 8 + lr];
                MMA_TF32(s[nt], a0, a1, a2, a3, b0, b1);
            }
        }

        if (kt == qt) {
#pragma unroll
            for (int nt = 0; nt < 16; nt++) {
                int c0 = nt * 8 + 2 * lc;
                int r0 = swm + lr, r1 = r0 + 8;
                if (c0 > r0)     s[nt][0] = -1e30f;
                if (c0 + 1 > r0) s[nt][1] = -1e30f;
                if (c0 > r1)     s[nt][2] = -1e30f;
                if (c0 + 1 > r1) s[nt][3] = -1e30f;
            }
        }

        float mx0 = -1e30f, mx1 = -1e30f;
#pragma unroll
        for (int nt = 0; nt < 16; nt++) {
            mx0 = fmaxf(mx0, fmaxf(s[nt][0], s[nt][1]));
            mx1 = fmaxf(mx1, fmaxf(s[nt][2], s[nt][3]));
        }
        mx0 = fmaxf(mx0, __shfl_xor_sync(0xffffffffu, mx0, 1));
        mx0 = fmaxf(mx0, __shfl_xor_sync(0xffffffffu, mx0, 2));
        mx1 = fmaxf(mx1, __shfl_xor_sync(0xffffffffu, mx1, 1));
        mx1 = fmaxf(mx1, __shfl_xor_sync(0xffffffffu, mx1, 2));
        float mn0 = fmaxf(mrow0, mx0), mn1 = fmaxf(mrow1, mx1);
        float sc0 = __expf(mrow0 - mn0), sc1 = __expf(mrow1 - mn1);

        float sum0 = 0.f, sum1 = 0.f;
#pragma unroll
        for (int nt = 0; nt < 16; nt++) {
            float p00 = __expf(s[nt][0] - mn0);
            float p01 = __expf(s[nt][1] - mn0);
            float p10 = __expf(s[nt][2] - mn1);
            float p11 = __expf(s[nt][3] - mn1);
            sum0 += p00 + p01;
            sum1 += p10 + p11;
            const int key = nt * 8 + 2 * lc;
            fs[OFF_P + (key + 0) * PSTR_F + swm + lr]     = f2tf32(p00);
            fs[OFF_P + (key + 1) * PSTR_F + swm + lr]     = f2tf32(p01);
            fs[OFF_P + (key + 0) * PSTR_F + swm + lr + 8] = f2tf32(p10);
            fs[OFF_P + (key + 1) * PSTR_F + swm + lr + 8] = f2tf32(p11);
        }
        sum0 += __shfl_xor_sync(0xffffffffu, sum0, 1);
        sum0 += __shfl_xor_sync(0xffffffffu, sum0, 2);
        sum1 += __shfl_xor_sync(0xffffffffu, sum1, 1);
        sum1 += __shfl_xor_sync(0xffffffffu, sum1, 2);
        lrow0 = lrow0 * sc0 + sum0;
        lrow1 = lrow1 * sc1 + sum1;
        mrow0 = mn0; mrow1 = mn1;
        if (lc == 0) {
            fsf[OFF_SC + swm + lr]     = sc0;
            fsf[OFF_SC + swm + lr + 8] = sc1;
        }
        __syncthreads();

        float rs[2][2];
        rs[0][0] = fsf[OFF_SC + owm + lr];
        rs[0][1] = fsf[OFF_SC + owm + lr + 8];
        rs[1][0] = fsf[OFF_SC + owm + 16 + lr];
        rs[1][1] = fsf[OFF_SC + owm + 16 + lr + 8];
#pragma unroll
        for (int mt = 0; mt < 2; mt++)
#pragma unroll
            for (int nt = 0; nt < 4; nt++) {
                oacc[mt][nt][0] *= rs[mt][0];
                oacc[mt][nt][1] *= rs[mt][0];
                oacc[mt][nt][2] *= rs[mt][1];
                oacc[mt][nt][3] *= rs[mt][1];
            }
#pragma unroll
        for (int ks = 0; ks < 16; ks++) {
            const int kk = ks * 8;
            uint32_t a[2][4];
#pragma unroll
            for (int mt = 0; mt < 2; mt++) {
                int m0 = owm + mt * 16 + lr;
                a[mt][0] = fs[OFF_P + (kk + lc) * PSTR_F + m0];
                a[mt][1] = fs[OFF_P + (kk + lc) * PSTR_F + m0 + 8];
                a[mt][2] = fs[OFF_P + (kk + lc + 4) * PSTR_F + m0];
                a[mt][3] = fs[OFF_P + (kk + lc + 4) * PSTR_F + m0 + 8];
            }
#pragma unroll
            for (int nt = 0; nt < 4; nt++) {
                uint32_t b0 = fs[OFF_V + (kk + lc) * VSTR_F + own + nt * 8 + lr];
                uint32_t b1 = fs[OFF_V + (kk + lc + 4) * VSTR_F + own + nt * 8 + lr];
#pragma unroll
                for (int mt = 0; mt < 2; mt++)
                    MMA_TF32(oacc[mt][nt], a[mt][0], a[mt][1], a[mt][2], a[mt][3], b0, b1);
            }
        }
        __syncthreads();
    }

    if (lc == 0) {
        fsf[OFF_L + swm + lr]     = 1.f / lrow0;
        fsf[OFF_L + swm + lr + 8] = 1.f / lrow1;
    }
    __syncthreads();
    float il[2][2];
    il[0][0] = fsf[OFF_L + owm + lr];
    il[0][1] = fsf[OFF_L + owm + lr + 8];
    il[1][0] = fsf[OFF_L + owm + 16 + lr];
    il[1][1] = fsf[OFF_L + owm + 16 + lr + 8];

#pragma unroll
    for (int mt = 0; mt < 2; mt++)
#pragma unroll
        for (int nt = 0; nt < 4; nt++) {
            int d = own + nt * 8 + 2 * lc;
#pragma unroll
            for (int hf = 0; hf < 2; hf++) {
                int r = owm + mt * 16 + lr + hf * 8;
                float v0 = rnd_tf32(oacc[mt][nt][hf * 2 + 0] * il[mt][hf]);
                float v1 = rnd_tf32(oacc[mt][nt][hf * 2 + 1] * il[mt][hf]);
                float* orow = ocat + (browq + r) * HDP_ + h * D_;
                if (d < D_)     orow[d] = v0;
                if (d + 1 < D_) orow[d + 1] = v1;
            }
        }
}

// ---------------- weight repacks (all outputs tf32-rounded) ----------------
__global__ void repack_qkv(const float* __restrict__ Wq, const float* __restrict__ Wk,
                           const float* __restrict__ Wv, float* __restrict__ Wp)
{
    ll idx = (ll)blockIdx.x * 256 + threadIdx.x;
    const ll total = (ll)L_ * E_ * QLD_;
    if (idx >= total) return;
    int c = (int)(idx % QLD_);
    ll le = idx / QLD_;
    int e = (int)(le % E_);
    int l = (int)(le / E_);
    int h = c / HB_, r = c % HB_, s = r >> 6, d = r & 63;
    float v = 0.f;
    if (d < D_) {
        const float* W = (s == 0) ? Wq : (s == 1) ? Wk : Wv;
        v = rnd_tf32(W[(((ll)l * H_ + h) * E_ + e) * D_ + d]);
    }
    Wp[idx] = v;
}
__global__ void repack_bias(const float* __restrict__ bq, const float* __restrict__ bk,
                            const float* __restrict__ bv, float* __restrict__ bp)
{
    int idx = blockIdx.x * 256 + threadIdx.x;
    if (idx >= L_ * QLD_) return;
    int c = idx % QLD_, l = idx / QLD_;
    int h = c / HB_, r = c % HB_, s = r >> 6, d = r & 63;
    float v = 0.f;
    if (d < D_) {
        const float* bb = (s == 0) ? bq : (s == 1) ? bk : bv;
        v = bb[((ll)l * H_ + h) * D_ + d];
    }
    bp[idx] = v;
}
__global__ void repack_wc(const float* __restrict__ Wc, float* __restrict__ Wp)
{
    ll idx = (ll)blockIdx.x * 256 + threadIdx.x;
    const ll total = (ll)L_ * HDP_ * E_;
    if (idx >= total) return;
    int e = (int)(idx % E_);
    ll lr = idx / E_;
    int r = (int)(lr % HDP_);
    int l = (int)(lr / HDP_);
    Wp[idx] = (r < HD_) ? rnd_tf32(Wc[((ll)l * HD_ + r) * E_ + e]) : 0.f;
}
__global__ void round_copy(const float* __restrict__ src, float* __restrict__ dst, ll n4)
{
    ll i = ((ll)blockIdx.x * 256 + threadIdx.x);
    if (i >= n4) return;
    float4 v = *reinterpret_cast<const float4*>(src + i * 4);
    v.x = rnd_tf32(v.x); v.y = rnd_tf32(v.y);
    v.z = rnd_tf32(v.z); v.w = rnd_tf32(v.w);
    *reinterpret_cast<float4*>(dst + i * 4) = v;
}

// ---------------- pointwise / reductions ----------------
__global__ void embed_kernel(const int* __restrict__ ids,
                             const float* __restrict__ tok,
                             const float* __restrict__ pos,
                             float* __restrict__ x)
{
    int row = blockIdx.x;
    int s = row % S_;
    ll id = ids[row];
    float* xr = x + (ll)row * E_;
    const float* tr = tok + id * E_;
    const float* pr = pos + (ll)s * E_;
    for (int i = threadIdx.x; i < E_; i += blockDim.x)
        xr[i] = tr[i] + pr[i];
}

__global__ void ln_kernel(const float* __restrict__ x,
                          const float* __restrict__ g,
                          const float* __restrict__ b,
                          float* __restrict__ y)
{
    int row = blockIdx.x;
    const float* xr = x + (ll)row * E_;
    float s = 0.f, ss = 0.f;
    for (int i = threadIdx.x; i < E_; i += 128) {
        float v = xr[i];
        s += v; ss += v * v;
    }
#pragma unroll
    for (int o = 16; o > 0; o >>= 1) {
        s  += __shfl_xor_sync(0xffffffffu, s, o);
        ss += __shfl_xor_sync(0xffffffffu, ss, o);
    }
    __shared__ float sh_s[4], sh_ss[4];
    int w = threadIdx.x >> 5;
    if ((threadIdx.x & 31) == 0) { sh_s[w] = s; sh_ss[w] = ss; }
    __syncthreads();
    s  = sh_s[0] + sh_s[1] + sh_s[2] + sh_s[3];
    ss = sh_ss[0] + sh_ss[1] + sh_ss[2] + sh_ss[3];
    float mean = s / E_;
    float var  = ss / E_ - mean * mean;
    float rstd = rsqrtf(var + EPS_);
    float* yr = y + (ll)row * E_;
    for (int i = threadIdx.x; i < E_; i += 128)
        yr[i] = rnd_tf32((xr[i] - mean) * rstd * g[i] + b[i]);
}

__global__ void loss_kernel(const float* __restrict__ logits,
                            const int* __restrict__ tgt,
                            float* __restrict__ acc)
{
    int row = blockIdx.x;
    const float* p = logits + (ll)row * V_;
    __shared__ float sh[8];
    float mx = -1e30f;
    for (int j = threadIdx.x; j < V_; j += 256) mx = fmaxf(mx, p[j]);
#pragma unroll
    for (int o = 16; o > 0; o >>= 1) mx = fmaxf(mx, __shfl_xor_sync(0xffffffffu, mx, o));
    int w = threadIdx.x >> 5;
    if ((threadIdx.x & 31) == 0) sh[w] = mx;
    __syncthreads();
    mx = sh[0];
#pragma unroll
    for (int i = 1; i < 8; i++) mx = fmaxf(mx, sh[i]);
    __syncthreads();
    float sum = 0.f;
    for (int j = threadIdx.x; j < V_; j += 256) sum += expf(p[j] - mx);
#pragma unroll
    for (int o = 16; o > 0; o >>= 1) sum += __shfl_xor_sync(0xffffffffu, sum, o);
    if ((threadIdx.x & 31) == 0) sh[w] = sum;
    __syncthreads();
    if (threadIdx.x == 0) {
        float tot = 0.f;
#pragma unroll
        for (int i = 0; i < 8; i++) tot += sh[i];
        float lse = mx + logf(tot);
        atomicAdd(acc, p[tgt[row]] - lse);
    }
}

__global__ void zero_loss(float* a) { *a = 0.f; }
__global__ void fin_loss(const float* a, float* out) { *out = -(*a) / (float)BS_; }

// ---------------- host driver ----------------
constexpr int SMEM_FLASH = FLASH_WORDS * 4;

static void gemm(const float* A, const float* Bm, const float* bias, float* C,
                 int M, int N, int K, int lda, int ldb, int ldc,
                 int batch, int zdiv,
                 ll sA1, ll sA2, ll sB1, ll sB2, ll sC1, ll sC2,
                 float alpha, int flags)
{
    dim3 grid((N + 127) / 128, M / 128, batch);
    tc_gemm<<<grid, 256, SMEM_GEMM>>>(
        A, Bm, bias, C, M, N, K, lda, ldb, ldc,
        zdiv, sA1, sA2, sB1, sB2, sC1, sC2, alpha, flags);
}

extern "C" void kernel_launch(void* const* d_in, const int* in_sizes, int n_in,
                              void* d_out, int out_size)
{
    const int*   input_ids = (const int*)d_in[0];
    const int*   targets   = (const int*)d_in[1];
    const float* tok_emb   = (const float*)d_in[2];
    const float* pos_emb   = (const float*)d_in[3];
    const float* Wq  = (const float*)d_in[4];
    const float* bq  = (const float*)d_in[5];
    const float* Wk  = (const float*)d_in[6];
    const float* bk  = (const float*)d_in[7];
    const float* Wv  = (const float*)d_in[8];
    const float* bv  = (const float*)d_in[9];
    const float* Wc  = (const float*)d_in[10];
    const float* bc  = (const float*)d_in[11];
    const float* g1  = (const float*)d_in[12];
    const float* b1  = (const float*)d_in[13];
    const float* g2  = (const float*)d_in[14];
    const float* b2  = (const float*)d_in[15];
    const float* W1  = (const float*)d_in[16];
    const float* bf1 = (const float*)d_in[17];
    const float* W2  = (const float*)d_in[18];
    const float* bf2 = (const float*)d_in[19];
    const float* gf   = (const float*)d_in[20];
    const float* bfin = (const float*)d_in[21];
    const float* Wout = (const float*)d_in[22];
    const float* bout = (const float*)d_in[23];
    float* out = (float*)d_out;

    cudaFuncSetAttribute(tc_gemm,
                         cudaFuncAttributeMaxDynamicSharedMemorySize, SMEM_GEMM);
    cudaFuncSetAttribute(flash_kernel,
                         cudaFuncAttributeMaxDynamicSharedMemorySize, SMEM_FLASH);

    float *x, *xn, *qkv, *wqkv, *bqkv, *wcp, *w1r, *w2r, *woutr, *ocat, *hbuf, *lossp;
    cudaGetSymbolAddress((void**)&x,    g_x);
    cudaGetSymbolAddress((void**)&xn,   g_xn);
    cudaGetSymbolAddress((void**)&qkv,  g_qkv);
    cudaGetSymbolAddress((void**)&wqkv, g_wqkv);
    cudaGetSymbolAddress((void**)&bqkv, g_bqkv);
    cudaGetSymbolAddress((void**)&wcp,  g_wc);
    cudaGetSymbolAddress((void**)&w1r,  g_w1r);
    cudaGetSymbolAddress((void**)&w2r,  g_w2r);
    cudaGetSymbolAddress((void**)&woutr, g_woutr);
    cudaGetSymbolAddress((void**)&ocat, g_ocat);
    cudaGetSymbolAddress((void**)&hbuf, g_h);
    cudaGetSymbolAddress((void**)&lossp, g_loss);

    {
        ll total = (ll)L_ * E_ * QLD_;
        repack_qkv<<<(int)((total + 255) / 256), 256>>>(Wq, Wk, Wv, wqkv);
        repack_bias<<<(L_ * QLD_ + 255) / 256, 256>>>(bq, bk, bv, bqkv);
        ll tot2 = (ll)L_ * HDP_ * E_;
        repack_wc<<<(int)((tot2 + 255) / 256), 256>>>(Wc, wcp);
        ll n1 = (ll)L_ * E_ * FF_ / 4;
        round_copy<<<(int)((n1 + 255) / 256), 256>>>(W1, w1r, n1);
        round_copy<<<(int)((n1 + 255) / 256), 256>>>(W2, w2r, n1);
        ll n2 = (ll)E_ * V_ / 4;
        round_copy<<<(int)((n2 + 255) / 256), 256>>>(Wout, woutr, n2);
    }

    embed_kernel<<<BS_, 128>>>(input_ids, tok_emb, pos_emb, x);

    for (int l = 0; l < L_; l++) {
        ln_kernel<<<BS_, 128>>>(x, g1 + l * E_, b1 + l * E_, xn);

        // fused QKV: [4096,384] @ [384,1344], output rounded for flash
        gemm(xn, wqkv + (ll)l * E_ * QLD_, bqkv + (ll)l * QLD_, qkv,
             BS_, QLD_, E_, E_, QLD_, QLD_,
             1, 1, 0, 0, 0, 0, 0, 0, 1.f, FLAG_RND);

        // fused causal attention -> ocat (rounded, stride 384)
        {
            dim3 grid(S_ / 128, B_ * H_);
            flash_kernel<<<grid, 256, SMEM_FLASH>>>(qkv, ocat);
        }

        // x += ocat @ Wc_pad + bc
        gemm(ocat, wcp + (ll)l * HDP_ * E_, bc + l * E_, x,
             BS_, E_, HDP_, HDP_, E_, E_,
             1, 1, 0, 0, 0, 0, 0, 0, 1.f, FLAG_ACC);

        ln_kernel<<<BS_, 128>>>(x, g2 + l * E_, b2 + l * E_, xn);

        // h = gelu(xn @ W1 + bf1), rounded for FF2
        gemm(xn, w1r + (ll)l * E_ * FF_, bf1 + (ll)l * FF_, hbuf,
             BS_, FF_, E_, E_, FF_, FF_,
             1, 1, 0, 0, 0, 0, 0, 0, 1.f, FLAG_GELU | FLAG_RND);

        // x += h @ W2 + bf2
        gemm(hbuf, w2r + (ll)l * FF_ * E_, bf2 + l * E_, x,
             BS_, E_, FF_, FF_, E_, E_,
             1, 1, 0, 0, 0, 0, 0, 0, 1.f, FLAG_ACC);
    }

    ln_kernel<<<BS_, 128>>>(x, gf, bfin, xn);
    gemm(xn, woutr, bout, out,
         BS_, V_, E_, E_, V_, V_,
         1, 1, 0, 0, 0, 0, 0, 0, 1.f, 0);

    const ll NLOG = (ll)BS_ * V_;
    if ((ll)out_size > NLOG) {
        zero_loss<<<1, 1>>>(lossp);
        loss_kernel<<<BS_, 256>>>(out, targets, lossp);
        fin_loss<<<1, 1>>>(lossp, out + NLOG);
    }
}